// round 1
// baseline (speedup 1.0000x reference)
#include <cuda_runtime.h>
#include <cstddef>

// Problem constants
#define BATCH 4
#define TSEQ  4096
#define EDIM  2048
#define DDIM  128
#define MTOT  (BATCH * TSEQ)   // 16384

// Scratch for Q, K, V projections (8 MB each)
__device__ float g_Q[MTOT * DDIM];
__device__ float g_K[MTOT * DDIM];
__device__ float g_V[MTOT * DDIM];

// ---------------------------------------------------------------------------
// Kernel 1: QKV projection GEMM.  Y = X @ W,  X[M,E] (fp32), W[E,D] (fp32).
// Block tile 128x128, K-tile 16, 256 threads, 8x8 per-thread micro-tile.
// grid.z selects which of {Wq, Wk, Wv} / {g_Q, g_K, g_V}.
// ---------------------------------------------------------------------------
#define GBM 128
#define GBN 128
#define GBK 16

__global__ __launch_bounds__(256)
void qkv_gemm_kernel(const float* __restrict__ x,
                     const float* __restrict__ Wq,
                     const float* __restrict__ Wk,
                     const float* __restrict__ Wv)
{
    const float* W = (blockIdx.z == 0) ? Wq : (blockIdx.z == 1) ? Wk : Wv;
    float* Y       = (blockIdx.z == 0) ? g_Q : (blockIdx.z == 1) ? g_K : g_V;

    __shared__ float Xs[GBK][GBM + 1];  // transposed X tile, padded
    __shared__ float Ws[GBK][GBN];

    const int tid = threadIdx.x;
    const int tx  = tid & 15;    // 0..15
    const int ty  = tid >> 4;    // 0..15
    const int row0 = blockIdx.x * GBM;

    float acc[8][8];
    #pragma unroll
    for (int m = 0; m < 8; m++)
        #pragma unroll
        for (int n = 0; n < 8; n++)
            acc[m][n] = 0.0f;

    for (int k0 = 0; k0 < EDIM; k0 += GBK) {
        // Load X tile: rows row0..row0+127, cols k0..k0+15  (2048 elems, 8/thread)
        #pragma unroll
        for (int i = 0; i < 8; i++) {
            int e = tid + i * 256;
            int r = e >> 4;
            int c = e & 15;
            Xs[c][r] = x[(size_t)(row0 + r) * EDIM + (k0 + c)];
        }
        // Load W tile: rows k0..k0+15, all 128 cols  (2048 elems, 8/thread)
        #pragma unroll
        for (int i = 0; i < 8; i++) {
            int e = tid + i * 256;
            int r = e >> 7;
            int c = e & 127;
            Ws[r][c] = W[(size_t)(k0 + r) * DDIM + c];
        }
        __syncthreads();

        #pragma unroll
        for (int k = 0; k < GBK; k++) {
            float rm[8], rn[8];
            #pragma unroll
            for (int m = 0; m < 8; m++) rm[m] = Xs[k][ty * 8 + m];
            #pragma unroll
            for (int n = 0; n < 8; n++) rn[n] = Ws[k][tx * 8 + n];
            #pragma unroll
            for (int m = 0; m < 8; m++)
                #pragma unroll
                for (int n = 0; n < 8; n++)
                    acc[m][n] += rm[m] * rn[n];
        }
        __syncthreads();
    }

    #pragma unroll
    for (int m = 0; m < 8; m++)
        #pragma unroll
        for (int n = 0; n < 8; n++)
            Y[(size_t)(row0 + ty * 8 + m) * DDIM + (tx * 8 + n)] = acc[m][n];
}

// ---------------------------------------------------------------------------
// Kernel 2: causal flash attention (fp32, online softmax).
// One block = one (batch, 64-row Q tile). 256 threads (16x16 thread grid).
//   S tile: thread computes 4x4 of a 64x64 score tile.
//   O tile: thread accumulates 4 rows x 8 cols of the 64x128 output tile.
// Dynamic smem: Qs/Ks/Vs 64x(128+4) each + Ps 64x(64+4)  = 118784 bytes.
// ---------------------------------------------------------------------------
#define BQ   64
#define BKV  64
#define DPAD (DDIM + 4)
#define PPAD (BKV + 4)
#define ATTN_SMEM_BYTES ((3 * BQ * DPAD + BQ * PPAD) * (int)sizeof(float))

__global__ __launch_bounds__(256)
void attn_kernel(float* __restrict__ out)
{
    extern __shared__ float smem[];
    float* Qs = smem;                        // [BQ][DPAD]
    float* Ks = Qs + BQ * DPAD;              // [BKV][DPAD]
    float* Vs = Ks + BKV * DPAD;             // [BKV][DPAD]
    float* Ps = Vs + BKV * DPAD;             // [BQ][PPAD]

    // Descending qi order for causal load balance (big blocks first).
    const int qi  = (gridDim.x - 1) - blockIdx.x;   // 0..63
    const int b   = blockIdx.y;                     // 0..3
    const int tid = threadIdx.x;
    const int tx  = tid & 15;
    const int ty  = tid >> 4;

    const float scale = 0.08838834764831845f;  // 1/sqrt(128)

    const float* Qg = g_Q + ((size_t)b * TSEQ + (size_t)qi * BQ) * DDIM;
    const float* Kg = g_K + (size_t)b * TSEQ * DDIM;
    const float* Vg = g_V + (size_t)b * TSEQ * DDIM;

    // Load Q tile (pre-scaled), float4 vectorized: 2048 float4, 8 per thread.
    {
        const float4* Qg4 = (const float4*)Qg;
        for (int i = tid; i < BQ * (DDIM / 4); i += 256) {
            int r  = i >> 5;        // row
            int c4 = i & 31;        // float4 col
            float4 v = Qg4[r * (DDIM / 4) + c4];
            v.x *= scale; v.y *= scale; v.z *= scale; v.w *= scale;
            *(float4*)&Qs[r * DPAD + c4 * 4] = v;
        }
    }

    float m_i[4], l_i[4];
    #pragma unroll
    for (int r = 0; r < 4; r++) { m_i[r] = -1e30f; l_i[r] = 0.0f; }
    float acc[4][8];
    #pragma unroll
    for (int r = 0; r < 4; r++)
        #pragma unroll
        for (int c = 0; c < 8; c++)
            acc[r][c] = 0.0f;

    for (int j = 0; j <= qi; j++) {
        __syncthreads();  // prior iteration's PV reads done before overwriting Ks/Vs/Ps

        // Load K, V tiles (float4 vectorized): 2048 float4 each, 8/thread each.
        {
            const float4* Kg4 = (const float4*)(Kg + (size_t)j * BKV * DDIM);
            const float4* Vg4 = (const float4*)(Vg + (size_t)j * BKV * DDIM);
            for (int i = tid; i < BKV * (DDIM / 4); i += 256) {
                int r  = i >> 5;
                int c4 = i & 31;
                *(float4*)&Ks[r * DPAD + c4 * 4] = Kg4[r * (DDIM / 4) + c4];
                *(float4*)&Vs[r * DPAD + c4 * 4] = Vg4[r * (DDIM / 4) + c4];
            }
        }
        __syncthreads();

        // S = Qs @ Ks^T : 4x4 per thread, k vectorized by 4.
        float s[4][4];
        #pragma unroll
        for (int mm = 0; mm < 4; mm++)
            #pragma unroll
            for (int nn = 0; nn < 4; nn++)
                s[mm][nn] = 0.0f;

        for (int k = 0; k < DDIM; k += 4) {
            float4 rq[4], rk[4];
            #pragma unroll
            for (int mm = 0; mm < 4; mm++)
                rq[mm] = *(const float4*)&Qs[(ty * 4 + mm) * DPAD + k];
            #pragma unroll
            for (int nn = 0; nn < 4; nn++)
                rk[nn] = *(const float4*)&Ks[(tx * 4 + nn) * DPAD + k];
            #pragma unroll
            for (int mm = 0; mm < 4; mm++)
                #pragma unroll
                for (int nn = 0; nn < 4; nn++)
                    s[mm][nn] += rq[mm].x * rk[nn].x + rq[mm].y * rk[nn].y
                               + rq[mm].z * rk[nn].z + rq[mm].w * rk[nn].w;
        }

        // Causal mask on the diagonal tile.
        if (j == qi) {
            #pragma unroll
            for (int mm = 0; mm < 4; mm++)
                #pragma unroll
                for (int nn = 0; nn < 4; nn++)
                    if (tx * 4 + nn > ty * 4 + mm) s[mm][nn] = -1e30f;
        }

        // Online softmax per row (row reduction across the 16 tx lanes).
        #pragma unroll
        for (int mm = 0; mm < 4; mm++) {
            float mx = fmaxf(fmaxf(s[mm][0], s[mm][1]), fmaxf(s[mm][2], s[mm][3]));
            #pragma unroll
            for (int o = 8; o >= 1; o >>= 1)
                mx = fmaxf(mx, __shfl_xor_sync(0xffffffffu, mx, o));
            float mnew = fmaxf(m_i[mm], mx);
            float f = __expf(m_i[mm] - mnew);
            float sum = 0.0f;
            #pragma unroll
            for (int nn = 0; nn < 4; nn++) {
                s[mm][nn] = __expf(s[mm][nn] - mnew);
                sum += s[mm][nn];
            }
            #pragma unroll
            for (int o = 8; o >= 1; o >>= 1)
                sum += __shfl_xor_sync(0xffffffffu, sum, o);
            l_i[mm] = l_i[mm] * f + sum;
            m_i[mm] = mnew;
            #pragma unroll
            for (int nn = 0; nn < 8; nn++) acc[mm][nn] *= f;
        }

        // Stage P to shared for the PV GEMM.
        #pragma unroll
        for (int mm = 0; mm < 4; mm++)
            #pragma unroll
            for (int nn = 0; nn < 4; nn++)
                Ps[(ty * 4 + mm) * PPAD + (tx * 4 + nn)] = s[mm][nn];
        __syncthreads();

        // O += P @ V : thread rows ty*4.., cols tx*8..
        for (int k = 0; k < BKV; k++) {
            float rp[4];
            #pragma unroll
            for (int mm = 0; mm < 4; mm++)
                rp[mm] = Ps[(ty * 4 + mm) * PPAD + k];
            float4 v0 = *(const float4*)&Vs[k * DPAD + tx * 8];
            float4 v1 = *(const float4*)&Vs[k * DPAD + tx * 8 + 4];
            #pragma unroll
            for (int mm = 0; mm < 4; mm++) {
                acc[mm][0] += rp[mm] * v0.x;
                acc[mm][1] += rp[mm] * v0.y;
                acc[mm][2] += rp[mm] * v0.z;
                acc[mm][3] += rp[mm] * v0.w;
                acc[mm][4] += rp[mm] * v1.x;
                acc[mm][5] += rp[mm] * v1.y;
                acc[mm][6] += rp[mm] * v1.z;
                acc[mm][7] += rp[mm] * v1.w;
            }
        }
    }

    // Epilogue: normalize and store.
    float* Og = out + ((size_t)b * TSEQ + (size_t)qi * BQ) * DDIM;
    #pragma unroll
    for (int mm = 0; mm < 4; mm++) {
        float inv = 1.0f / l_i[mm];
        #pragma unroll
        for (int nn = 0; nn < 8; nn++)
            Og[(size_t)(ty * 4 + mm) * DDIM + (tx * 8 + nn)] = acc[mm][nn] * inv;
    }
}

// ---------------------------------------------------------------------------
// Launch
// ---------------------------------------------------------------------------
extern "C" void kernel_launch(void* const* d_in, const int* in_sizes, int n_in,
                              void* d_out, int out_size)
{
    (void)in_sizes; (void)n_in; (void)out_size;
    const float* x  = (const float*)d_in[0];
    const float* Wq = (const float*)d_in[1];
    const float* Wk = (const float*)d_in[2];
    const float* Wv = (const float*)d_in[3];
    float* out = (float*)d_out;

    // QKV projections: 128 M-tiles x 3 matrices.
    dim3 g1(MTOT / GBM, 1, 3);
    qkv_gemm_kernel<<<g1, 256>>>(x, Wq, Wk, Wv);

    // Attention: 64 Q-tiles x 4 batches, 116 KB dynamic smem.
    cudaFuncSetAttribute(attn_kernel,
                         cudaFuncAttributeMaxDynamicSharedMemorySize,
                         ATTN_SMEM_BYTES);
    dim3 g2(TSEQ / BQ, BATCH);
    attn_kernel<<<g2, 256, ATTN_SMEM_BYTES>>>(out);
}

// round 3
// speedup vs baseline: 4.4513x; 4.4513x over previous
#include <cuda_runtime.h>
#include <cstdint>
#include <cstddef>

// ---------------------------------------------------------------------------
// Problem constants
// ---------------------------------------------------------------------------
#define BATCH 4
#define TSEQ  4096
#define EDIM  2048
#define DDIM  128
#define MTOT  (BATCH * TSEQ)   // 16384

// Scratch for Q, K, V projections (8 MB each)
__device__ float g_Q[MTOT * DDIM];
__device__ float g_K[MTOT * DDIM];
__device__ float g_V[MTOT * DDIM];

// ---------------------------------------------------------------------------
// Helpers: tf32 convert + mma.sync (sm_80+ PTX, legal on family target sm_103)
// ---------------------------------------------------------------------------
__device__ __forceinline__ uint32_t f2tf32(float f) {
    uint32_t u;
    asm("cvt.rna.tf32.f32 %0, %1;" : "=r"(u) : "f"(f));
    return u;
}

// D(16x8,f32) += A(16x8,tf32,row) * B(8x8,tf32,col)
// A frags: a0=A[l>>2][l&3] a1=A[(l>>2)+8][l&3] a2=A[l>>2][(l&3)+4] a3=A[(l>>2)+8][(l&3)+4]
// B frags: b0=B[l&3][l>>2] b1=B[(l&3)+4][l>>2]
// D frags: d0=D[l>>2][2(l&3)] d1=+1col d2=D[(l>>2)+8][2(l&3)] d3=+1col
__device__ __forceinline__ void mma_tf32(float* d, const uint32_t* a, const uint32_t* b) {
    asm volatile(
        "mma.sync.aligned.m16n8k8.row.col.f32.tf32.tf32.f32 "
        "{%0,%1,%2,%3}, {%4,%5,%6,%7}, {%8,%9}, {%0,%1,%2,%3};\n"
        : "+f"(d[0]), "+f"(d[1]), "+f"(d[2]), "+f"(d[3])
        : "r"(a[0]), "r"(a[1]), "r"(a[2]), "r"(a[3]),
          "r"(b[0]), "r"(b[1]));
}

// ---------------------------------------------------------------------------
// Kernel 1: QKV projection GEMM on tensor cores (tf32).
//   grid (3, 128): z = {Q,K,V} fastest-varying -> co-scheduled CTAs share the
//   x M-tile in L2. CTA tile 128x128, KC=64, 8 warps (warp tile 32x64).
//   SMEM strides 68 / 132 (both == 4 mod 32 -> conflict-free frag loads).
// ---------------------------------------------------------------------------
#define GKC   64
#define ASTR  68
#define BSTR  132
#define GEMM_SMEM ((128 * ASTR + GKC * BSTR) * 4)   // 68608 bytes

__global__ __launch_bounds__(256, 2)
void qkv_mma_kernel(const float* __restrict__ x,
                    const float* __restrict__ Wq,
                    const float* __restrict__ Wk,
                    const float* __restrict__ Wv)
{
    extern __shared__ uint32_t smg[];
    uint32_t* As = smg;                   // [128][ASTR] tf32
    uint32_t* Bs = smg + 128 * ASTR;      // [GKC][BSTR] tf32

    const int z = blockIdx.x;
    const float* W = (z == 0) ? Wq : (z == 1) ? Wk : Wv;
    float* Y       = (z == 0) ? g_Q : (z == 1) ? g_K : g_V;
    const int row0 = blockIdx.y * 128;

    const int tid  = threadIdx.x;
    const int lane = tid & 31;
    const int wid  = tid >> 5;
    const int wm   = wid >> 1;    // 0..3 (32 rows each)
    const int wn   = wid & 1;     // 0..1 (64 cols each)

    float acc[2][8][4];
    #pragma unroll
    for (int mt = 0; mt < 2; mt++)
        #pragma unroll
        for (int nt = 0; nt < 8; nt++)
            #pragma unroll
            for (int q = 0; q < 4; q++)
                acc[mt][nt][q] = 0.0f;

    for (int k0 = 0; k0 < EDIM; k0 += GKC) {
        // Load A tile: x[row0..+127][k0..+63] -> tf32 SMEM
        #pragma unroll
        for (int t = tid; t < 2048; t += 256) {
            int r = t >> 4, c4 = t & 15;
            float4 v = *(const float4*)(x + (size_t)(row0 + r) * EDIM + k0 + c4 * 4);
            uint4 u;
            u.x = f2tf32(v.x); u.y = f2tf32(v.y);
            u.z = f2tf32(v.z); u.w = f2tf32(v.w);
            *(uint4*)(As + r * ASTR + c4 * 4) = u;
        }
        // Load B tile: W[k0..+63][0..127] -> tf32 SMEM ([k][n])
        #pragma unroll
        for (int t = tid; t < 2048; t += 256) {
            int k = t >> 5, n4 = t & 31;
            float4 v = *(const float4*)(W + (size_t)(k0 + k) * DDIM + n4 * 4);
            uint4 u;
            u.x = f2tf32(v.x); u.y = f2tf32(v.y);
            u.z = f2tf32(v.z); u.w = f2tf32(v.w);
            *(uint4*)(Bs + k * BSTR + n4 * 4) = u;
        }
        __syncthreads();

        #pragma unroll
        for (int ks = 0; ks < GKC / 8; ks++) {
            uint32_t a[2][4];
            const int ak = ks * 8 + (lane & 3);
            #pragma unroll
            for (int mt = 0; mt < 2; mt++) {
                const int ar = wm * 32 + mt * 16 + (lane >> 2);
                a[mt][0] = As[ar * ASTR + ak];
                a[mt][1] = As[(ar + 8) * ASTR + ak];
                a[mt][2] = As[ar * ASTR + ak + 4];
                a[mt][3] = As[(ar + 8) * ASTR + ak + 4];
            }
            uint32_t bf[8][2];
            const int bk  = ks * 8 + (lane & 3);
            const int bn0 = wn * 64 + (lane >> 2);
            #pragma unroll
            for (int nt = 0; nt < 8; nt++) {
                bf[nt][0] = Bs[bk * BSTR + bn0 + nt * 8];
                bf[nt][1] = Bs[(bk + 4) * BSTR + bn0 + nt * 8];
            }
            #pragma unroll
            for (int mt = 0; mt < 2; mt++)
                #pragma unroll
                for (int nt = 0; nt < 8; nt++)
                    mma_tf32(acc[mt][nt], a[mt], bf[nt]);
        }
        __syncthreads();
    }

    // Epilogue: D frags -> fp32 gmem (float2 stores)
    #pragma unroll
    for (int mt = 0; mt < 2; mt++) {
        const int r0 = row0 + wm * 32 + mt * 16 + (lane >> 2);
        #pragma unroll
        for (int nt = 0; nt < 8; nt++) {
            const int col = wn * 64 + nt * 8 + 2 * (lane & 3);
            float2 lo = make_float2(acc[mt][nt][0], acc[mt][nt][1]);
            float2 hi = make_float2(acc[mt][nt][2], acc[mt][nt][3]);
            *(float2*)(Y + (size_t)r0 * DDIM + col)       = lo;
            *(float2*)(Y + (size_t)(r0 + 8) * DDIM + col) = hi;
        }
    }
}

// ---------------------------------------------------------------------------
// Kernel 2: causal flash attention on tensor cores (tf32).
//   128 threads, 4 warps; each warp owns a 16-row slice of a 64-row Q tile
//   (softmax reductions stay intra-quad). BKV=64 per iteration.
// ---------------------------------------------------------------------------
#define BQ    64
#define BKV   64
#define QSTR  132
#define PSTR  68
#define ATT_SMEM ((3 * 64 * QSTR + 64 * PSTR) * 4)   // 118784 bytes

__global__ __launch_bounds__(128, 1)
void attn_mma_kernel(float* __restrict__ out)
{
    extern __shared__ uint32_t sma[];
    uint32_t* Qs = sma;                   // [64][QSTR] tf32 (pre-scaled)
    uint32_t* Ks = Qs + 64 * QSTR;        // [64][QSTR] tf32
    uint32_t* Vs = Ks + 64 * QSTR;        // [64][QSTR] tf32
    uint32_t* Ps = Vs + 64 * QSTR;        // [64][PSTR] tf32

    const int qi  = (gridDim.x - 1) - blockIdx.x;   // reversed: big blocks first
    const int b   = blockIdx.y;
    const int tid  = threadIdx.x;
    const int lane = tid & 31;
    const int wid  = tid >> 5;            // 0..3

    const float scale = 0.08838834764831845f;  // 1/sqrt(128)

    const float* Qg = g_Q + ((size_t)b * TSEQ + (size_t)qi * BQ) * DDIM;
    const float* Kg = g_K + (size_t)b * TSEQ * DDIM;
    const float* Vg = g_V + (size_t)b * TSEQ * DDIM;

    // Load + scale + convert Q tile.
    {
        const float4* Qg4 = (const float4*)Qg;
        #pragma unroll
        for (int i = tid; i < BQ * (DDIM / 4); i += 128) {
            int r = i >> 5, c4 = i & 31;
            float4 v = Qg4[r * (DDIM / 4) + c4];
            uint4 u;
            u.x = f2tf32(v.x * scale); u.y = f2tf32(v.y * scale);
            u.z = f2tf32(v.z * scale); u.w = f2tf32(v.w * scale);
            *(uint4*)(Qs + r * QSTR + c4 * 4) = u;
        }
    }

    float m0 = -1e30f, m1 = -1e30f, l0 = 0.0f, l1 = 0.0f;
    float o[16][4];
    #pragma unroll
    for (int nt = 0; nt < 16; nt++)
        #pragma unroll
        for (int q = 0; q < 4; q++)
            o[nt][q] = 0.0f;

    for (int j = 0; j <= qi; j++) {
        __syncthreads();   // prior PV reads of Ks/Vs complete

        // Load K, V tiles (tf32)
        {
            const float4* Kg4 = (const float4*)(Kg + (size_t)j * BKV * DDIM);
            const float4* Vg4 = (const float4*)(Vg + (size_t)j * BKV * DDIM);
            #pragma unroll
            for (int i = tid; i < BKV * (DDIM / 4); i += 128) {
                int r = i >> 5, c4 = i & 31;
                float4 kv = Kg4[r * (DDIM / 4) + c4];
                float4 vv = Vg4[r * (DDIM / 4) + c4];
                uint4 uk, uv;
                uk.x = f2tf32(kv.x); uk.y = f2tf32(kv.y);
                uk.z = f2tf32(kv.z); uk.w = f2tf32(kv.w);
                uv.x = f2tf32(vv.x); uv.y = f2tf32(vv.y);
                uv.z = f2tf32(vv.z); uv.w = f2tf32(vv.w);
                *(uint4*)(Ks + r * QSTR + c4 * 4) = uk;
                *(uint4*)(Vs + r * QSTR + c4 * 4) = uv;
            }
        }
        __syncthreads();

        // ---- S = Q K^T : warp computes 16x64, 8 n-tiles x 16 k-steps ----
        float s[8][4];
        #pragma unroll
        for (int nt = 0; nt < 8; nt++)
            #pragma unroll
            for (int q = 0; q < 4; q++)
                s[nt][q] = 0.0f;

        #pragma unroll
        for (int ks = 0; ks < DDIM / 8; ks++) {
            uint32_t a[4];
            const int ar = wid * 16 + (lane >> 2);
            const int ak = ks * 8 + (lane & 3);
            a[0] = Qs[ar * QSTR + ak];
            a[1] = Qs[(ar + 8) * QSTR + ak];
            a[2] = Qs[ar * QSTR + ak + 4];
            a[3] = Qs[(ar + 8) * QSTR + ak + 4];
            #pragma unroll
            for (int nt = 0; nt < 8; nt++) {
                uint32_t bf[2];
                const int bn = nt * 8 + (lane >> 2);
                bf[0] = Ks[bn * QSTR + ak];
                bf[1] = Ks[bn * QSTR + ak + 4];
                mma_tf32(s[nt], a, bf);
            }
        }

        // Causal mask on the diagonal block.
        if (j == qi) {
            const int rl0 = wid * 16 + (lane >> 2);
            #pragma unroll
            for (int nt = 0; nt < 8; nt++) {
                const int c0 = nt * 8 + 2 * (lane & 3);
                if (c0     > rl0)     s[nt][0] = -1e30f;
                if (c0 + 1 > rl0)     s[nt][1] = -1e30f;
                if (c0     > rl0 + 8) s[nt][2] = -1e30f;
                if (c0 + 1 > rl0 + 8) s[nt][3] = -1e30f;
            }
        }

        // ---- Online softmax (2 rows per thread, quad reductions) ----
        float mx0 = -1e30f, mx1 = -1e30f;
        #pragma unroll
        for (int nt = 0; nt < 8; nt++) {
            mx0 = fmaxf(mx0, fmaxf(s[nt][0], s[nt][1]));
            mx1 = fmaxf(mx1, fmaxf(s[nt][2], s[nt][3]));
        }
        mx0 = fmaxf(mx0, __shfl_xor_sync(0xffffffffu, mx0, 1));
        mx0 = fmaxf(mx0, __shfl_xor_sync(0xffffffffu, mx0, 2));
        mx1 = fmaxf(mx1, __shfl_xor_sync(0xffffffffu, mx1, 1));
        mx1 = fmaxf(mx1, __shfl_xor_sync(0xffffffffu, mx1, 2));

        const float mn0 = fmaxf(m0, mx0);
        const float mn1 = fmaxf(m1, mx1);
        const float f0 = __expf(m0 - mn0);
        const float f1 = __expf(m1 - mn1);

        float sum0 = 0.0f, sum1 = 0.0f;
        #pragma unroll
        for (int nt = 0; nt < 8; nt++) {
            s[nt][0] = __expf(s[nt][0] - mn0);
            s[nt][1] = __expf(s[nt][1] - mn0);
            s[nt][2] = __expf(s[nt][2] - mn1);
            s[nt][3] = __expf(s[nt][3] - mn1);
            sum0 += s[nt][0] + s[nt][1];
            sum1 += s[nt][2] + s[nt][3];
        }
        sum0 += __shfl_xor_sync(0xffffffffu, sum0, 1);
        sum0 += __shfl_xor_sync(0xffffffffu, sum0, 2);
        sum1 += __shfl_xor_sync(0xffffffffu, sum1, 1);
        sum1 += __shfl_xor_sync(0xffffffffu, sum1, 2);

        l0 = l0 * f0 + sum0;  m0 = mn0;
        l1 = l1 * f1 + sum1;  m1 = mn1;

        #pragma unroll
        for (int nt = 0; nt < 16; nt++) {
            o[nt][0] *= f0; o[nt][1] *= f0;
            o[nt][2] *= f1; o[nt][3] *= f1;
        }

        // Stage P (tf32) — warp-private rows, so __syncwarp suffices.
        {
            const int pr = wid * 16 + (lane >> 2);
            const int pc = 2 * (lane & 3);
            #pragma unroll
            for (int nt = 0; nt < 8; nt++) {
                Ps[pr * PSTR + nt * 8 + pc]           = f2tf32(s[nt][0]);
                Ps[pr * PSTR + nt * 8 + pc + 1]       = f2tf32(s[nt][1]);
                Ps[(pr + 8) * PSTR + nt * 8 + pc]     = f2tf32(s[nt][2]);
                Ps[(pr + 8) * PSTR + nt * 8 + pc + 1] = f2tf32(s[nt][3]);
            }
        }
        __syncwarp();

        // ---- O += P V : 16 n-tiles x 8 k-steps ----
        #pragma unroll
        for (int ks = 0; ks < BKV / 8; ks++) {
            uint32_t a[4];
            const int ar = wid * 16 + (lane >> 2);
            const int ak = ks * 8 + (lane & 3);
            a[0] = Ps[ar * PSTR + ak];
            a[1] = Ps[(ar + 8) * PSTR + ak];
            a[2] = Ps[ar * PSTR + ak + 4];
            a[3] = Ps[(ar + 8) * PSTR + ak + 4];
            #pragma unroll
            for (int nt = 0; nt < 16; nt++) {
                uint32_t bf[2];
                const int bn = nt * 8 + (lane >> 2);
                bf[0] = Vs[(ks * 8 + (lane & 3)) * QSTR + bn];
                bf[1] = Vs[(ks * 8 + (lane & 3) + 4) * QSTR + bn];
                mma_tf32(o[nt], a, bf);
            }
        }
    }

    // Epilogue: normalize, store.
    const float inv0 = 1.0f / l0;
    const float inv1 = 1.0f / l1;
    const int rg = qi * BQ + wid * 16 + (lane >> 2);
    float* Og = out + ((size_t)b * TSEQ) * DDIM;
    #pragma unroll
    for (int nt = 0; nt < 16; nt++) {
        const int col = nt * 8 + 2 * (lane & 3);
        float2 lo = make_float2(o[nt][0] * inv0, o[nt][1] * inv0);
        float2 hi = make_float2(o[nt][2] * inv1, o[nt][3] * inv1);
        *(float2*)(Og + (size_t)rg * DDIM + col)       = lo;
        *(float2*)(Og + (size_t)(rg + 8) * DDIM + col) = hi;
    }
}

// ---------------------------------------------------------------------------
// Launch
// ---------------------------------------------------------------------------
extern "C" void kernel_launch(void* const* d_in, const int* in_sizes, int n_in,
                              void* d_out, int out_size)
{
    (void)in_sizes; (void)n_in; (void)out_size;
    const float* x  = (const float*)d_in[0];
    const float* Wq = (const float*)d_in[1];
    const float* Wk = (const float*)d_in[2];
    const float* Wv = (const float*)d_in[3];
    float* out = (float*)d_out;

    cudaFuncSetAttribute(qkv_mma_kernel,
                         cudaFuncAttributeMaxDynamicSharedMemorySize, GEMM_SMEM);
    dim3 g1(3, MTOT / 128);   // z fastest -> Q/K/V CTAs share x tile in L2
    qkv_mma_kernel<<<g1, 256, GEMM_SMEM>>>(x, Wq, Wk, Wv);

    cudaFuncSetAttribute(attn_mma_kernel,
                         cudaFuncAttributeMaxDynamicSharedMemorySize, ATT_SMEM);
    dim3 g2(TSEQ / BQ, BATCH);
    attn_mma_kernel<<<g2, 128, ATT_SMEM>>>(out);
}

// round 4
// speedup vs baseline: 5.3472x; 1.2013x over previous
#include <cuda_runtime.h>
#include <cstdint>
#include <cstddef>

// ---------------------------------------------------------------------------
// Problem constants
// ---------------------------------------------------------------------------
#define BATCH 4
#define TSEQ  4096
#define EDIM  2048
#define DDIM  128
#define MTOT  (BATCH * TSEQ)   // 16384

__device__ float g_Q[MTOT * DDIM];
__device__ float g_K[MTOT * DDIM];
__device__ float g_V[MTOT * DDIM];

// ---------------------------------------------------------------------------
// Helpers
// ---------------------------------------------------------------------------
__device__ __forceinline__ uint32_t f2tf32(float f) {
    uint32_t u;
    asm("cvt.rna.tf32.f32 %0, %1;" : "=r"(u) : "f"(f));
    return u;
}

__device__ __forceinline__ uint32_t smem_u32(const void* p) {
    uint32_t a;
    asm("{ .reg .u64 t; cvta.to.shared.u64 t, %1; cvt.u32.u64 %0, t; }"
        : "=r"(a) : "l"(p));
    return a;
}

__device__ __forceinline__ void cp_async16(uint32_t saddr, const void* gptr) {
    asm volatile("cp.async.cg.shared.global [%0], [%1], 16;"
                 :: "r"(saddr), "l"(gptr));
}
#define CP_COMMIT() asm volatile("cp.async.commit_group;" ::: "memory")
#define CP_WAIT(n)  asm volatile("cp.async.wait_group %0;" :: "n"(n) : "memory")

// D(16x8,f32) += A(16x8,tf32,row) * B(8x8,tf32,col)
__device__ __forceinline__ void mma_tf32(float* d, const uint32_t* a, const uint32_t* b) {
    asm volatile(
        "mma.sync.aligned.m16n8k8.row.col.f32.tf32.tf32.f32 "
        "{%0,%1,%2,%3}, {%4,%5,%6,%7}, {%8,%9}, {%0,%1,%2,%3};\n"
        : "+f"(d[0]), "+f"(d[1]), "+f"(d[2]), "+f"(d[3])
        : "r"(a[0]), "r"(a[1]), "r"(a[2]), "r"(a[3]),
          "r"(b[0]), "r"(b[1]));
}

// ---------------------------------------------------------------------------
// Kernel 1: QKV projection GEMM (tf32 mma), cp.async 2-stage pipeline.
//   CTA tile 128x128, KC=32, 8 warps (warp tile 32x64), fp32 smem + cvt@load.
//   grid (3, 128): z fastest -> Q/K/V CTAs of one M-tile share x in L2.
//   Q output pre-scaled by 1/sqrt(D).
// ---------------------------------------------------------------------------
#define GKC   32
#define ASTR  36      // fp32 words per A row (32 + 4 pad)
#define BSTR  132     // fp32 words per B row (128 + 4 pad)
#define ABUF  (128 * ASTR)         // words per A stage
#define BBUF  (GKC * BSTR)         // words per B stage
#define GEMM_SMEM ((2 * ABUF + 2 * BBUF) * 4)   // 70656 bytes

__global__ __launch_bounds__(256, 2)
void qkv_mma_kernel(const float* __restrict__ x,
                    const float* __restrict__ Wq,
                    const float* __restrict__ Wk,
                    const float* __restrict__ Wv)
{
    extern __shared__ float smg[];
    float* As = smg;                 // [2][128][ASTR]
    float* Bs = smg + 2 * ABUF;      // [2][GKC][BSTR]
    const uint32_t as_b = smem_u32(As);
    const uint32_t bs_b = smem_u32(Bs);

    const int z = blockIdx.x;
    const float* W = (z == 0) ? Wq : (z == 1) ? Wk : Wv;
    float* Y       = (z == 0) ? g_Q : (z == 1) ? g_K : g_V;
    const int row0 = blockIdx.y * 128;

    const int tid  = threadIdx.x;
    const int lane = tid & 31;
    const int wid  = tid >> 5;
    const int wm   = wid >> 1;    // 0..3
    const int wn   = wid & 1;     // 0..1

    float acc[2][8][4];
    #pragma unroll
    for (int mt = 0; mt < 2; mt++)
        #pragma unroll
        for (int nt = 0; nt < 8; nt++)
            #pragma unroll
            for (int q = 0; q < 4; q++)
                acc[mt][nt][q] = 0.0f;

    // Issue one k-chunk's cp.async loads into stage `buf`.
    auto issue = [&](int c, int buf) {
        const int k0 = c * GKC;
        // A: 128 rows x 32 floats = 1024 16B chunks, 4 per thread
        #pragma unroll
        for (int t = 0; t < 4; t++) {
            int e = tid + t * 256;
            int r = e >> 3, c16 = e & 7;
            cp_async16(as_b + (uint32_t)buf * ABUF * 4 + (uint32_t)(r * ASTR + c16 * 4) * 4,
                       x + (size_t)(row0 + r) * EDIM + k0 + c16 * 4);
        }
        // B: 32 rows x 128 floats = 1024 16B chunks, 4 per thread
        #pragma unroll
        for (int t = 0; t < 4; t++) {
            int e = tid + t * 256;
            int r = e >> 5, c16 = e & 31;
            cp_async16(bs_b + (uint32_t)buf * BBUF * 4 + (uint32_t)(r * BSTR + c16 * 4) * 4,
                       W + (size_t)(k0 + r) * DDIM + c16 * 4);
        }
    };

    issue(0, 0);
    CP_COMMIT();

    const int NCH = EDIM / GKC;   // 64
    for (int c = 0; c < NCH; c++) {
        if (c < NCH - 1) { issue(c + 1, (c + 1) & 1); CP_COMMIT(); CP_WAIT(1); }
        else             { CP_WAIT(0); }
        __syncthreads();

        const float* Asb = As + (c & 1) * ABUF;
        const float* Bsb = Bs + (c & 1) * BBUF;

        #pragma unroll
        for (int ks = 0; ks < GKC / 8; ks++) {
            const int ak = ks * 8 + (lane & 3);
            uint32_t a[2][4];
            #pragma unroll
            for (int mt = 0; mt < 2; mt++) {
                const int ar = wm * 32 + mt * 16 + (lane >> 2);
                a[mt][0] = f2tf32(Asb[ar * ASTR + ak]);
                a[mt][1] = f2tf32(Asb[(ar + 8) * ASTR + ak]);
                a[mt][2] = f2tf32(Asb[ar * ASTR + ak + 4]);
                a[mt][3] = f2tf32(Asb[(ar + 8) * ASTR + ak + 4]);
            }
            uint32_t bf[8][2];
            const int bn0 = wn * 64 + (lane >> 2);
            #pragma unroll
            for (int nt = 0; nt < 8; nt++) {
                bf[nt][0] = f2tf32(Bsb[ak * BSTR + bn0 + nt * 8]);
                bf[nt][1] = f2tf32(Bsb[(ak + 4) * BSTR + bn0 + nt * 8]);
            }
            #pragma unroll
            for (int mt = 0; mt < 2; mt++)
                #pragma unroll
                for (int nt = 0; nt < 8; nt++)
                    mma_tf32(acc[mt][nt], a[mt], bf[nt]);
        }
        __syncthreads();
    }

    // Epilogue (Q gets 1/sqrt(D) folded in)
    const float sc = (z == 0) ? 0.08838834764831845f : 1.0f;
    #pragma unroll
    for (int mt = 0; mt < 2; mt++) {
        const int r0 = row0 + wm * 32 + mt * 16 + (lane >> 2);
        #pragma unroll
        for (int nt = 0; nt < 8; nt++) {
            const int col = wn * 64 + nt * 8 + 2 * (lane & 3);
            float2 lo = make_float2(acc[mt][nt][0] * sc, acc[mt][nt][1] * sc);
            float2 hi = make_float2(acc[mt][nt][2] * sc, acc[mt][nt][3] * sc);
            *(float2*)(Y + (size_t)r0 * DDIM + col)       = lo;
            *(float2*)(Y + (size_t)(r0 + 8) * DDIM + col) = hi;
        }
    }
}

// ---------------------------------------------------------------------------
// Kernel 2: causal flash attention (tf32 mma).
//   BQ=64 (4 warps x 16 rows), BKV=32, cp.async double-buffered K/V (fp32),
//   Q fragments in registers, 2 CTAs/SM, work-balanced 1D grid.
// ---------------------------------------------------------------------------
#define BQ    64
#define BKV   32
#define KSTR  132                       // fp32 words per K/V row
#define PSTR  36                        // tf32 words per P row
#define KBUF  (BKV * KSTR)              // 4224 words per stage
#define ATT_SMEM ((4 * KBUF + BQ * PSTR) * 4)   // 76800 bytes

__global__ __launch_bounds__(128, 2)
void attn_mma_kernel(float* __restrict__ out)
{
    extern __shared__ float sma[];
    float* Kb = sma;                    // [2][BKV][KSTR]
    float* Vb = sma + 2 * KBUF;         // [2][BKV][KSTR]
    uint32_t* Ps = (uint32_t*)(sma + 4 * KBUF);   // [BQ][PSTR] tf32
    const uint32_t kb_b = smem_u32(Kb);
    const uint32_t vb_b = smem_u32(Vb);

    // Work-balanced ordering: bid and bid+148 land on the same SM (classic
    // placement), so pair big CTAs with small ones: rank = bid or 403-bid.
    const int bid  = blockIdx.x;
    const int rank = (bid < 148) ? bid : (403 - bid);
    const int qi   = 63 - (rank >> 2);
    const int b    = rank & 3;

    const int tid  = threadIdx.x;
    const int lane = tid & 31;
    const int wid  = tid >> 5;          // 0..3

    const float* Qg = g_Q + ((size_t)b * TSEQ + (size_t)qi * BQ) * DDIM;
    const float* Kg = g_K + (size_t)b * TSEQ * DDIM;
    const float* Vg = g_V + (size_t)b * TSEQ * DDIM;

    // Q fragments in registers (scale already folded in by the GEMM).
    uint32_t qf[16][4];
    {
        const int ar = wid * 16 + (lane >> 2);
        #pragma unroll
        for (int ks = 0; ks < 16; ks++) {
            const int ak = ks * 8 + (lane & 3);
            qf[ks][0] = f2tf32(Qg[(size_t)ar * DDIM + ak]);
            qf[ks][1] = f2tf32(Qg[(size_t)(ar + 8) * DDIM + ak]);
            qf[ks][2] = f2tf32(Qg[(size_t)ar * DDIM + ak + 4]);
            qf[ks][3] = f2tf32(Qg[(size_t)(ar + 8) * DDIM + ak + 4]);
        }
    }

    auto issue = [&](int j, int buf) {
        const float* kg = Kg + (size_t)j * BKV * DDIM;
        const float* vg = Vg + (size_t)j * BKV * DDIM;
        const uint32_t kd = kb_b + (uint32_t)buf * KBUF * 4;
        const uint32_t vd = vb_b + (uint32_t)buf * KBUF * 4;
        #pragma unroll
        for (int t = 0; t < 8; t++) {
            int e = tid + t * 128;           // 0..1023
            int r = e >> 5, c16 = e & 31;
            uint32_t off = (uint32_t)(r * KSTR + c16 * 4) * 4;
            cp_async16(kd + off, kg + (size_t)r * DDIM + c16 * 4);
            cp_async16(vd + off, vg + (size_t)r * DDIM + c16 * 4);
        }
    };

    float m0 = -1e30f, m1 = -1e30f, l0 = 0.0f, l1 = 0.0f;
    float o[16][4];
    #pragma unroll
    for (int nt = 0; nt < 16; nt++)
        #pragma unroll
        for (int q = 0; q < 4; q++)
            o[nt][q] = 0.0f;

    const int jmax = 2 * qi + 1;
    issue(0, 0);
    CP_COMMIT();

    for (int j = 0; j <= jmax; j++) {
        if (j < jmax) { issue(j + 1, (j + 1) & 1); CP_COMMIT(); CP_WAIT(1); }
        else          { CP_WAIT(0); }
        __syncthreads();

        const float* Ksb = Kb + (j & 1) * KBUF;
        const float* Vsb = Vb + (j & 1) * KBUF;

        // Warp-uniform skip of fully-masked diagonal tiles.
        const bool active = (j * BKV <= qi * BQ + wid * 16 + 15);
        if (active) {
            // ---- S = Q K^T : 4 n-tiles x 16 k-steps ----
            float s[4][4];
            #pragma unroll
            for (int nt = 0; nt < 4; nt++)
                #pragma unroll
                for (int q = 0; q < 4; q++)
                    s[nt][q] = 0.0f;

            #pragma unroll
            for (int ks = 0; ks < 16; ks++) {
                const int ak = ks * 8 + (lane & 3);
                #pragma unroll
                for (int nt = 0; nt < 4; nt++) {
                    const int bn = nt * 8 + (lane >> 2);
                    uint32_t bf[2];
                    bf[0] = f2tf32(Ksb[bn * KSTR + ak]);
                    bf[1] = f2tf32(Ksb[bn * KSTR + ak + 4]);
                    mma_tf32(s[nt], qf[ks], bf);
                }
            }

            // Causal mask (only on tiles straddling the diagonal).
            if (j * BKV + BKV - 1 > qi * BQ + wid * 16) {
                const int grow = qi * BQ + wid * 16 + (lane >> 2);
                #pragma unroll
                for (int nt = 0; nt < 4; nt++) {
                    const int gc = j * BKV + nt * 8 + 2 * (lane & 3);
                    if (gc     > grow)     s[nt][0] = -1e30f;
                    if (gc + 1 > grow)     s[nt][1] = -1e30f;
                    if (gc     > grow + 8) s[nt][2] = -1e30f;
                    if (gc + 1 > grow + 8) s[nt][3] = -1e30f;
                }
            }

            // ---- Online softmax (2 rows/thread, quad reductions) ----
            float mx0 = -1e30f, mx1 = -1e30f;
            #pragma unroll
            for (int nt = 0; nt < 4; nt++) {
                mx0 = fmaxf(mx0, fmaxf(s[nt][0], s[nt][1]));
                mx1 = fmaxf(mx1, fmaxf(s[nt][2], s[nt][3]));
            }
            mx0 = fmaxf(mx0, __shfl_xor_sync(0xffffffffu, mx0, 1));
            mx0 = fmaxf(mx0, __shfl_xor_sync(0xffffffffu, mx0, 2));
            mx1 = fmaxf(mx1, __shfl_xor_sync(0xffffffffu, mx1, 1));
            mx1 = fmaxf(mx1, __shfl_xor_sync(0xffffffffu, mx1, 2));

            const float mn0 = fmaxf(m0, mx0);
            const float mn1 = fmaxf(m1, mx1);
            const float f0 = __expf(m0 - mn0);
            const float f1 = __expf(m1 - mn1);

            float sum0 = 0.0f, sum1 = 0.0f;
            #pragma unroll
            for (int nt = 0; nt < 4; nt++) {
                s[nt][0] = __expf(s[nt][0] - mn0);
                s[nt][1] = __expf(s[nt][1] - mn0);
                s[nt][2] = __expf(s[nt][2] - mn1);
                s[nt][3] = __expf(s[nt][3] - mn1);
                sum0 += s[nt][0] + s[nt][1];
                sum1 += s[nt][2] + s[nt][3];
            }
            sum0 += __shfl_xor_sync(0xffffffffu, sum0, 1);
            sum0 += __shfl_xor_sync(0xffffffffu, sum0, 2);
            sum1 += __shfl_xor_sync(0xffffffffu, sum1, 1);
            sum1 += __shfl_xor_sync(0xffffffffu, sum1, 2);

            l0 = l0 * f0 + sum0;  m0 = mn0;
            l1 = l1 * f1 + sum1;  m1 = mn1;

            #pragma unroll
            for (int nt = 0; nt < 16; nt++) {
                o[nt][0] *= f0; o[nt][1] *= f0;
                o[nt][2] *= f1; o[nt][3] *= f1;
            }

            // Stage P (tf32), warp-private rows.
            {
                const int pr = wid * 16 + (lane >> 2);
                const int pc = 2 * (lane & 3);
                #pragma unroll
                for (int nt = 0; nt < 4; nt++) {
                    Ps[pr * PSTR + nt * 8 + pc]           = f2tf32(s[nt][0]);
                    Ps[pr * PSTR + nt * 8 + pc + 1]       = f2tf32(s[nt][1]);
                    Ps[(pr + 8) * PSTR + nt * 8 + pc]     = f2tf32(s[nt][2]);
                    Ps[(pr + 8) * PSTR + nt * 8 + pc + 1] = f2tf32(s[nt][3]);
                }
            }
            __syncwarp();

            // ---- O += P V : 16 n-tiles x 4 k-steps ----
            #pragma unroll
            for (int ks = 0; ks < BKV / 8; ks++) {
                const int ar = wid * 16 + (lane >> 2);
                const int ak = ks * 8 + (lane & 3);
                uint32_t a[4];
                a[0] = Ps[ar * PSTR + ak];
                a[1] = Ps[(ar + 8) * PSTR + ak];
                a[2] = Ps[ar * PSTR + ak + 4];
                a[3] = Ps[(ar + 8) * PSTR + ak + 4];
                #pragma unroll
                for (int nt = 0; nt < 16; nt++) {
                    const int bn = nt * 8 + (lane >> 2);
                    uint32_t bf[2];
                    bf[0] = f2tf32(Vsb[(ks * 8 + (lane & 3)) * KSTR + bn]);
                    bf[1] = f2tf32(Vsb[(ks * 8 + (lane & 3) + 4) * KSTR + bn]);
                    mma_tf32(o[nt], a, bf);
                }
            }
        }
        __syncthreads();
    }

    // Epilogue
    const float inv0 = 1.0f / l0;
    const float inv1 = 1.0f / l1;
    const int rg = qi * BQ + wid * 16 + (lane >> 2);
    float* Og = out + (size_t)b * TSEQ * DDIM;
    #pragma unroll
    for (int nt = 0; nt < 16; nt++) {
        const int col = nt * 8 + 2 * (lane & 3);
        float2 lo = make_float2(o[nt][0] * inv0, o[nt][1] * inv0);
        float2 hi = make_float2(o[nt][2] * inv1, o[nt][3] * inv1);
        *(float2*)(Og + (size_t)rg * DDIM + col)       = lo;
        *(float2*)(Og + (size_t)(rg + 8) * DDIM + col) = hi;
    }
}

// ---------------------------------------------------------------------------
// Launch
// ---------------------------------------------------------------------------
extern "C" void kernel_launch(void* const* d_in, const int* in_sizes, int n_in,
                              void* d_out, int out_size)
{
    (void)in_sizes; (void)n_in; (void)out_size;
    const float* x  = (const float*)d_in[0];
    const float* Wq = (const float*)d_in[1];
    const float* Wk = (const float*)d_in[2];
    const float* Wv = (const float*)d_in[3];
    float* out = (float*)d_out;

    cudaFuncSetAttribute(qkv_mma_kernel,
                         cudaFuncAttributeMaxDynamicSharedMemorySize, GEMM_SMEM);
    dim3 g1(3, MTOT / 128);
    qkv_mma_kernel<<<g1, 256, GEMM_SMEM>>>(x, Wq, Wk, Wv);

    cudaFuncSetAttribute(attn_mma_kernel,
                         cudaFuncAttributeMaxDynamicSharedMemorySize, ATT_SMEM);
    attn_mma_kernel<<<(TSEQ / BQ) * BATCH, 128, ATT_SMEM>>>(out);
}

// round 5
// speedup vs baseline: 5.4980x; 1.0282x over previous
#include <cuda_runtime.h>
#include <cstdint>
#include <cstddef>

// ---------------------------------------------------------------------------
// Problem constants
// ---------------------------------------------------------------------------
#define BATCH 4
#define TSEQ  4096
#define EDIM  2048
#define DDIM  128
#define MTOT  (BATCH * TSEQ)   // 16384

// Q (pre-scaled), K, V stored as tf32 bit patterns (uint32).
__device__ uint32_t g_Q[MTOT * DDIM];
__device__ uint32_t g_K[MTOT * DDIM];
__device__ uint32_t g_V[MTOT * DDIM];

// ---------------------------------------------------------------------------
// Helpers
// ---------------------------------------------------------------------------
__device__ __forceinline__ uint32_t f2tf32(float f) {
    uint32_t u;
    asm("cvt.rna.tf32.f32 %0, %1;" : "=r"(u) : "f"(f));
    return u;
}

__device__ __forceinline__ uint32_t smem_u32(const void* p) {
    uint32_t a;
    asm("{ .reg .u64 t; cvta.to.shared.u64 t, %1; cvt.u32.u64 %0, t; }"
        : "=r"(a) : "l"(p));
    return a;
}

__device__ __forceinline__ void cp_async16(uint32_t saddr, const void* gptr) {
    asm volatile("cp.async.cg.shared.global [%0], [%1], 16;"
                 :: "r"(saddr), "l"(gptr));
}
#define CP_COMMIT() asm volatile("cp.async.commit_group;" ::: "memory")
#define CP_WAIT(n)  asm volatile("cp.async.wait_group %0;" :: "n"(n) : "memory")

// D(16x8,f32) += A(16x8,tf32,row) * B(8x8,tf32,col)
__device__ __forceinline__ void mma_tf32(float* d, const uint32_t* a, const uint32_t* b) {
    asm volatile(
        "mma.sync.aligned.m16n8k8.row.col.f32.tf32.tf32.f32 "
        "{%0,%1,%2,%3}, {%4,%5,%6,%7}, {%8,%9}, {%0,%1,%2,%3};\n"
        : "+f"(d[0]), "+f"(d[1]), "+f"(d[2]), "+f"(d[3])
        : "r"(a[0]), "r"(a[1]), "r"(a[2]), "r"(a[3]),
          "r"(b[0]), "r"(b[1]));
}

// ---------------------------------------------------------------------------
// Kernel 1: QKV projection GEMM (tf32 mma), cp.async 2-stage pipeline.
//   CTA tile 128x128, KC=32, 8 warps (warp tile 32x64).
//   Outputs stored as tf32 bits; Q pre-scaled by 1/sqrt(D).
// ---------------------------------------------------------------------------
#define GKC   32
#define ASTR  36
#define BSTR  132
#define ABUF  (128 * ASTR)
#define BBUF  (GKC * BSTR)
#define GEMM_SMEM ((2 * ABUF + 2 * BBUF) * 4)   // 70656 bytes

__global__ __launch_bounds__(256, 2)
void qkv_mma_kernel(const float* __restrict__ x,
                    const float* __restrict__ Wq,
                    const float* __restrict__ Wk,
                    const float* __restrict__ Wv)
{
    extern __shared__ float smg[];
    float* As = smg;
    float* Bs = smg + 2 * ABUF;
    const uint32_t as_b = smem_u32(As);
    const uint32_t bs_b = smem_u32(Bs);

    const int z = blockIdx.x;
    const float* W = (z == 0) ? Wq : (z == 1) ? Wk : Wv;
    uint32_t* Y    = (z == 0) ? g_Q : (z == 1) ? g_K : g_V;
    const int row0 = blockIdx.y * 128;

    const int tid  = threadIdx.x;
    const int lane = tid & 31;
    const int wid  = tid >> 5;
    const int wm   = wid >> 1;
    const int wn   = wid & 1;

    float acc[2][8][4];
    #pragma unroll
    for (int mt = 0; mt < 2; mt++)
        #pragma unroll
        for (int nt = 0; nt < 8; nt++)
            #pragma unroll
            for (int q = 0; q < 4; q++)
                acc[mt][nt][q] = 0.0f;

    auto issue = [&](int c, int buf) {
        const int k0 = c * GKC;
        #pragma unroll
        for (int t = 0; t < 4; t++) {
            int e = tid + t * 256;
            int r = e >> 3, c16 = e & 7;
            cp_async16(as_b + (uint32_t)buf * ABUF * 4 + (uint32_t)(r * ASTR + c16 * 4) * 4,
                       x + (size_t)(row0 + r) * EDIM + k0 + c16 * 4);
        }
        #pragma unroll
        for (int t = 0; t < 4; t++) {
            int e = tid + t * 256;
            int r = e >> 5, c16 = e & 31;
            cp_async16(bs_b + (uint32_t)buf * BBUF * 4 + (uint32_t)(r * BSTR + c16 * 4) * 4,
                       W + (size_t)(k0 + r) * DDIM + c16 * 4);
        }
    };

    issue(0, 0);
    CP_COMMIT();

    const int NCH = EDIM / GKC;   // 64
    for (int c = 0; c < NCH; c++) {
        if (c < NCH - 1) { issue(c + 1, (c + 1) & 1); CP_COMMIT(); CP_WAIT(1); }
        else             { CP_WAIT(0); }
        __syncthreads();

        const float* Asb = As + (c & 1) * ABUF;
        const float* Bsb = Bs + (c & 1) * BBUF;

        #pragma unroll
        for (int ks = 0; ks < GKC / 8; ks++) {
            const int ak = ks * 8 + (lane & 3);
            uint32_t a[2][4];
            #pragma unroll
            for (int mt = 0; mt < 2; mt++) {
                const int ar = wm * 32 + mt * 16 + (lane >> 2);
                a[mt][0] = f2tf32(Asb[ar * ASTR + ak]);
                a[mt][1] = f2tf32(Asb[(ar + 8) * ASTR + ak]);
                a[mt][2] = f2tf32(Asb[ar * ASTR + ak + 4]);
                a[mt][3] = f2tf32(Asb[(ar + 8) * ASTR + ak + 4]);
            }
            uint32_t bf[8][2];
            const int bn0 = wn * 64 + (lane >> 2);
            #pragma unroll
            for (int nt = 0; nt < 8; nt++) {
                bf[nt][0] = f2tf32(Bsb[ak * BSTR + bn0 + nt * 8]);
                bf[nt][1] = f2tf32(Bsb[(ak + 4) * BSTR + bn0 + nt * 8]);
            }
            #pragma unroll
            for (int mt = 0; mt < 2; mt++)
                #pragma unroll
                for (int nt = 0; nt < 8; nt++)
                    mma_tf32(acc[mt][nt], a[mt], bf[nt]);
        }
        __syncthreads();
    }

    // Epilogue: cvt to tf32 bits once here (Q gets 1/sqrt(D) folded in).
    const float sc = (z == 0) ? 0.08838834764831845f : 1.0f;
    #pragma unroll
    for (int mt = 0; mt < 2; mt++) {
        const int r0 = row0 + wm * 32 + mt * 16 + (lane >> 2);
        #pragma unroll
        for (int nt = 0; nt < 8; nt++) {
            const int col = wn * 64 + nt * 8 + 2 * (lane & 3);
            uint2 lo = make_uint2(f2tf32(acc[mt][nt][0] * sc), f2tf32(acc[mt][nt][1] * sc));
            uint2 hi = make_uint2(f2tf32(acc[mt][nt][2] * sc), f2tf32(acc[mt][nt][3] * sc));
            *(uint2*)(Y + (size_t)r0 * DDIM + col)       = lo;
            *(uint2*)(Y + (size_t)(r0 + 8) * DDIM + col) = hi;
        }
    }
}

// ---------------------------------------------------------------------------
// Kernel 2: causal flash attention (tf32 mma).
//   BQ=64 (4 warps x 16 rows), BKV=32. Q/K/V already tf32 in gmem -> no cvt
//   in the hot loop. Q tile in SMEM (loaded once via cp.async). K/V double-
//   buffered cp.async. 2 CTAs/SM. Work-balanced 1D grid.
// ---------------------------------------------------------------------------
#define BQ    64
#define BKV   32
#define QSTR  132
#define KSTR  132
#define PSTR  36
#define QWORDS (BQ * QSTR)              // 8448
#define KBUF   (BKV * KSTR)             // 4224 per stage
#define ATT_SMEM ((QWORDS + 4 * KBUF + BQ * PSTR) * 4)   // 110592 bytes

__global__ __launch_bounds__(128, 2)
void attn_mma_kernel(float* __restrict__ out)
{
    extern __shared__ uint32_t sma[];
    uint32_t* Qs = sma;                       // [BQ][QSTR]
    uint32_t* Kb = sma + QWORDS;              // [2][BKV][KSTR]
    uint32_t* Vb = Kb + 2 * KBUF;             // [2][BKV][KSTR]
    uint32_t* Ps = Vb + 2 * KBUF;             // [BQ][PSTR]
    const uint32_t qs_b = smem_u32(Qs);
    const uint32_t kb_b = smem_u32(Kb);
    const uint32_t vb_b = smem_u32(Vb);

    // bid and bid+148 land on the same SM; pair big with small.
    const int bid  = blockIdx.x;
    const int rank = (bid < 148) ? bid : (403 - bid);
    const int qi   = 63 - (rank >> 2);
    const int b    = rank & 3;

    const int tid  = threadIdx.x;
    const int lane = tid & 31;
    const int wid  = tid >> 5;

    const uint32_t* Qg = g_Q + ((size_t)b * TSEQ + (size_t)qi * BQ) * DDIM;
    const uint32_t* Kg = g_K + (size_t)b * TSEQ * DDIM;
    const uint32_t* Vg = g_V + (size_t)b * TSEQ * DDIM;

    auto issue_kv = [&](int j, int buf) {
        const uint32_t* kg = Kg + (size_t)j * BKV * DDIM;
        const uint32_t* vg = Vg + (size_t)j * BKV * DDIM;
        const uint32_t kd = kb_b + (uint32_t)buf * KBUF * 4;
        const uint32_t vd = vb_b + (uint32_t)buf * KBUF * 4;
        #pragma unroll
        for (int t = 0; t < 8; t++) {
            int e = tid + t * 128;
            int r = e >> 5, c16 = e & 31;
            uint32_t off = (uint32_t)(r * KSTR + c16 * 4) * 4;
            cp_async16(kd + off, kg + (size_t)r * DDIM + c16 * 4);
            cp_async16(vd + off, vg + (size_t)r * DDIM + c16 * 4);
        }
    };

    // Group 0: Q tile + KV tile 0.
    #pragma unroll
    for (int t = 0; t < 16; t++) {            // 64 rows x 32 c16-chunks
        int e = tid + t * 128;
        int r = e >> 5, c16 = e & 31;
        cp_async16(qs_b + (uint32_t)(r * QSTR + c16 * 4) * 4,
                   Qg + (size_t)r * DDIM + c16 * 4);
    }
    issue_kv(0, 0);
    CP_COMMIT();

    float m0 = -1e30f, m1 = -1e30f, l0 = 0.0f, l1 = 0.0f;
    float o[16][4];
    #pragma unroll
    for (int nt = 0; nt < 16; nt++)
        #pragma unroll
        for (int q = 0; q < 4; q++)
            o[nt][q] = 0.0f;

    const int jmax = 2 * qi + 1;
    for (int j = 0; j <= jmax; j++) {
        if (j < jmax) { issue_kv(j + 1, (j + 1) & 1); CP_COMMIT(); CP_WAIT(1); }
        else          { CP_WAIT(0); }
        __syncthreads();

        const uint32_t* Ksb = Kb + (j & 1) * KBUF;
        const uint32_t* Vsb = Vb + (j & 1) * KBUF;

        const bool active = (j * BKV <= qi * BQ + wid * 16 + 15);
        if (active) {
            // ---- S = Q K^T ----
            float s[4][4];
            #pragma unroll
            for (int nt = 0; nt < 4; nt++)
                #pragma unroll
                for (int q = 0; q < 4; q++)
                    s[nt][q] = 0.0f;

            const int ar = wid * 16 + (lane >> 2);
            #pragma unroll
            for (int ks = 0; ks < 16; ks++) {
                const int ak = ks * 8 + (lane & 3);
                uint32_t a[4];
                a[0] = Qs[ar * QSTR + ak];
                a[1] = Qs[(ar + 8) * QSTR + ak];
                a[2] = Qs[ar * QSTR + ak + 4];
                a[3] = Qs[(ar + 8) * QSTR + ak + 4];
                #pragma unroll
                for (int nt = 0; nt < 4; nt++) {
                    const int bn = nt * 8 + (lane >> 2);
                    uint32_t bf[2];
                    bf[0] = Ksb[bn * KSTR + ak];
                    bf[1] = Ksb[bn * KSTR + ak + 4];
                    mma_tf32(s[nt], a, bf);
                }
            }

            // Causal mask (diagonal-straddling tiles only).
            if (j * BKV + BKV - 1 > qi * BQ + wid * 16) {
                const int grow = qi * BQ + wid * 16 + (lane >> 2);
                #pragma unroll
                for (int nt = 0; nt < 4; nt++) {
                    const int gc = j * BKV + nt * 8 + 2 * (lane & 3);
                    if (gc     > grow)     s[nt][0] = -1e30f;
                    if (gc + 1 > grow)     s[nt][1] = -1e30f;
                    if (gc     > grow + 8) s[nt][2] = -1e30f;
                    if (gc + 1 > grow + 8) s[nt][3] = -1e30f;
                }
            }

            // ---- Online softmax ----
            float mx0 = -1e30f, mx1 = -1e30f;
            #pragma unroll
            for (int nt = 0; nt < 4; nt++) {
                mx0 = fmaxf(mx0, fmaxf(s[nt][0], s[nt][1]));
                mx1 = fmaxf(mx1, fmaxf(s[nt][2], s[nt][3]));
            }
            mx0 = fmaxf(mx0, __shfl_xor_sync(0xffffffffu, mx0, 1));
            mx0 = fmaxf(mx0, __shfl_xor_sync(0xffffffffu, mx0, 2));
            mx1 = fmaxf(mx1, __shfl_xor_sync(0xffffffffu, mx1, 1));
            mx1 = fmaxf(mx1, __shfl_xor_sync(0xffffffffu, mx1, 2));

            const float mn0 = fmaxf(m0, mx0);
            const float mn1 = fmaxf(m1, mx1);
            const float f0 = __expf(m0 - mn0);
            const float f1 = __expf(m1 - mn1);

            float sum0 = 0.0f, sum1 = 0.0f;
            #pragma unroll
            for (int nt = 0; nt < 4; nt++) {
                s[nt][0] = __expf(s[nt][0] - mn0);
                s[nt][1] = __expf(s[nt][1] - mn0);
                s[nt][2] = __expf(s[nt][2] - mn1);
                s[nt][3] = __expf(s[nt][3] - mn1);
                sum0 += s[nt][0] + s[nt][1];
                sum1 += s[nt][2] + s[nt][3];
            }
            sum0 += __shfl_xor_sync(0xffffffffu, sum0, 1);
            sum0 += __shfl_xor_sync(0xffffffffu, sum0, 2);
            sum1 += __shfl_xor_sync(0xffffffffu, sum1, 1);
            sum1 += __shfl_xor_sync(0xffffffffu, sum1, 2);

            l0 = l0 * f0 + sum0;  m0 = mn0;
            l1 = l1 * f1 + sum1;  m1 = mn1;

            #pragma unroll
            for (int nt = 0; nt < 16; nt++) {
                o[nt][0] *= f0; o[nt][1] *= f0;
                o[nt][2] *= f1; o[nt][3] *= f1;
            }

            // Stage P (tf32), warp-private rows.
            {
                const int pr = wid * 16 + (lane >> 2);
                const int pc = 2 * (lane & 3);
                #pragma unroll
                for (int nt = 0; nt < 4; nt++) {
                    Ps[pr * PSTR + nt * 8 + pc]           = f2tf32(s[nt][0]);
                    Ps[pr * PSTR + nt * 8 + pc + 1]       = f2tf32(s[nt][1]);
                    Ps[(pr + 8) * PSTR + nt * 8 + pc]     = f2tf32(s[nt][2]);
                    Ps[(pr + 8) * PSTR + nt * 8 + pc + 1] = f2tf32(s[nt][3]);
                }
            }
            __syncwarp();

            // ---- O += P V ----
            #pragma unroll
            for (int ks = 0; ks < BKV / 8; ks++) {
                const int ak = ks * 8 + (lane & 3);
                uint32_t a[4];
                a[0] = Ps[ar * PSTR + ak];
                a[1] = Ps[(ar + 8) * PSTR + ak];
                a[2] = Ps[ar * PSTR + ak + 4];
                a[3] = Ps[(ar + 8) * PSTR + ak + 4];
                #pragma unroll
                for (int nt = 0; nt < 16; nt++) {
                    const int bn = nt * 8 + (lane >> 2);
                    uint32_t bf[2];
                    bf[0] = Vsb[(ks * 8 + (lane & 3)) * KSTR + bn];
                    bf[1] = Vsb[(ks * 8 + (lane & 3) + 4) * KSTR + bn];
                    mma_tf32(o[nt], a, bf);
                }
            }
        }
        __syncthreads();
    }

    // Epilogue
    const float inv0 = 1.0f / l0;
    const float inv1 = 1.0f / l1;
    const int rg = qi * BQ + wid * 16 + (lane >> 2);
    float* Og = out + (size_t)b * TSEQ * DDIM;
    #pragma unroll
    for (int nt = 0; nt < 16; nt++) {
        const int col = nt * 8 + 2 * (lane & 3);
        float2 lo = make_float2(o[nt][0] * inv0, o[nt][1] * inv0);
        float2 hi = make_float2(o[nt][2] * inv1, o[nt][3] * inv1);
        *(float2*)(Og + (size_t)rg * DDIM + col)       = lo;
        *(float2*)(Og + (size_t)(rg + 8) * DDIM + col) = hi;
    }
}

// ---------------------------------------------------------------------------
// Launch
// ---------------------------------------------------------------------------
extern "C" void kernel_launch(void* const* d_in, const int* in_sizes, int n_in,
                              void* d_out, int out_size)
{
    (void)in_sizes; (void)n_in; (void)out_size;
    const float* x  = (const float*)d_in[0];
    const float* Wq = (const float*)d_in[1];
    const float* Wk = (const float*)d_in[2];
    const float* Wv = (const float*)d_in[3];
    float* out = (float*)d_out;

    cudaFuncSetAttribute(qkv_mma_kernel,
                         cudaFuncAttributeMaxDynamicSharedMemorySize, GEMM_SMEM);
    dim3 g1(3, MTOT / 128);
    qkv_mma_kernel<<<g1, 256, GEMM_SMEM>>>(x, Wq, Wk, Wv);

    cudaFuncSetAttribute(attn_mma_kernel,
                         cudaFuncAttributeMaxDynamicSharedMemorySize, ATT_SMEM);
    attn_mma_kernel<<<(TSEQ / BQ) * BATCH, 128, ATT_SMEM>>>(out);
}

// round 6
// speedup vs baseline: 7.8967x; 1.4363x over previous
#include <cuda_runtime.h>
#include <cuda_fp16.h>
#include <cstdint>
#include <cstddef>

// ---------------------------------------------------------------------------
// Problem constants
// ---------------------------------------------------------------------------
#define BATCH 4
#define TSEQ  4096
#define EDIM  2048
#define DDIM  128
#define MTOT  (BATCH * TSEQ)   // 16384

// Q (pre-scaled by log2e/sqrt(D)), K, V stored as fp16 (4 MB each).
__device__ __half g_Q[MTOT * DDIM];
__device__ __half g_K[MTOT * DDIM];
__device__ __half g_V[MTOT * DDIM];

// ---------------------------------------------------------------------------
// Helpers
// ---------------------------------------------------------------------------
__device__ __forceinline__ uint32_t f2tf32(float f) {
    uint32_t u;
    asm("cvt.rna.tf32.f32 %0, %1;" : "=r"(u) : "f"(f));
    return u;
}

__device__ __forceinline__ uint32_t smem_u32(const void* p) {
    uint32_t a;
    asm("{ .reg .u64 t; cvta.to.shared.u64 t, %1; cvt.u32.u64 %0, t; }"
        : "=r"(a) : "l"(p));
    return a;
}

__device__ __forceinline__ void cp_async16(uint32_t saddr, const void* gptr) {
    asm volatile("cp.async.cg.shared.global [%0], [%1], 16;"
                 :: "r"(saddr), "l"(gptr));
}
#define CP_COMMIT() asm volatile("cp.async.commit_group;" ::: "memory")
#define CP_WAIT(n)  asm volatile("cp.async.wait_group %0;" :: "n"(n) : "memory")

__device__ __forceinline__ float ex2f(float x) {
    float r;
    asm("ex2.approx.ftz.f32 %0, %1;" : "=f"(r) : "f"(x));
    return r;
}

__device__ __forceinline__ uint32_t packh2(float a, float b) {
    __half2 h = __floats2half2_rn(a, b);   // low = a, high = b
    return *(uint32_t*)&h;
}

// tf32 mma for the projection GEMM
__device__ __forceinline__ void mma_tf32(float* d, const uint32_t* a, const uint32_t* b) {
    asm volatile(
        "mma.sync.aligned.m16n8k8.row.col.f32.tf32.tf32.f32 "
        "{%0,%1,%2,%3}, {%4,%5,%6,%7}, {%8,%9}, {%0,%1,%2,%3};\n"
        : "+f"(d[0]), "+f"(d[1]), "+f"(d[2]), "+f"(d[3])
        : "r"(a[0]), "r"(a[1]), "r"(a[2]), "r"(a[3]),
          "r"(b[0]), "r"(b[1]));
}

// fp16 mma, fp32 accumulate: D(16x8) += A(16x16) * B(16x8)
__device__ __forceinline__ void mma_f16(float* d, const uint32_t* a, const uint32_t* b) {
    asm volatile(
        "mma.sync.aligned.m16n8k16.row.col.f32.f16.f16.f32 "
        "{%0,%1,%2,%3}, {%4,%5,%6,%7}, {%8,%9}, {%0,%1,%2,%3};\n"
        : "+f"(d[0]), "+f"(d[1]), "+f"(d[2]), "+f"(d[3])
        : "r"(a[0]), "r"(a[1]), "r"(a[2]), "r"(a[3]),
          "r"(b[0]), "r"(b[1]));
}

__device__ __forceinline__ void ldsm_x4(uint32_t& r0, uint32_t& r1,
                                        uint32_t& r2, uint32_t& r3, uint32_t a) {
    asm volatile("ldmatrix.sync.aligned.m8n8.x4.shared.b16 {%0,%1,%2,%3}, [%4];"
                 : "=r"(r0), "=r"(r1), "=r"(r2), "=r"(r3) : "r"(a));
}
__device__ __forceinline__ void ldsm_x4_t(uint32_t& r0, uint32_t& r1,
                                          uint32_t& r2, uint32_t& r3, uint32_t a) {
    asm volatile("ldmatrix.sync.aligned.m8n8.x4.trans.shared.b16 {%0,%1,%2,%3}, [%4];"
                 : "=r"(r0), "=r"(r1), "=r"(r2), "=r"(r3) : "r"(a));
}

// ---------------------------------------------------------------------------
// Kernel 1: QKV projection GEMM (tf32 mma), cp.async 2-stage pipeline.
//   Outputs stored fp16; Q pre-scaled by log2(e)/sqrt(D) for base-2 softmax.
// ---------------------------------------------------------------------------
#define GKC   32
#define ASTR  36
#define BSTR  132
#define ABUF  (128 * ASTR)
#define BBUF  (GKC * BSTR)
#define GEMM_SMEM ((2 * ABUF + 2 * BBUF) * 4)   // 70656 bytes

__global__ __launch_bounds__(256, 2)
void qkv_mma_kernel(const float* __restrict__ x,
                    const float* __restrict__ Wq,
                    const float* __restrict__ Wk,
                    const float* __restrict__ Wv)
{
    extern __shared__ float smg[];
    float* As = smg;
    float* Bs = smg + 2 * ABUF;
    const uint32_t as_b = smem_u32(As);
    const uint32_t bs_b = smem_u32(Bs);

    const int z = blockIdx.x;
    const float* W = (z == 0) ? Wq : (z == 1) ? Wk : Wv;
    __half* Y      = (z == 0) ? g_Q : (z == 1) ? g_K : g_V;
    const int row0 = blockIdx.y * 128;

    const int tid  = threadIdx.x;
    const int lane = tid & 31;
    const int wid  = tid >> 5;
    const int wm   = wid >> 1;
    const int wn   = wid & 1;

    float acc[2][8][4];
    #pragma unroll
    for (int mt = 0; mt < 2; mt++)
        #pragma unroll
        for (int nt = 0; nt < 8; nt++)
            #pragma unroll
            for (int q = 0; q < 4; q++)
                acc[mt][nt][q] = 0.0f;

    auto issue = [&](int c, int buf) {
        const int k0 = c * GKC;
        #pragma unroll
        for (int t = 0; t < 4; t++) {
            int e = tid + t * 256;
            int r = e >> 3, c16 = e & 7;
            cp_async16(as_b + (uint32_t)buf * ABUF * 4 + (uint32_t)(r * ASTR + c16 * 4) * 4,
                       x + (size_t)(row0 + r) * EDIM + k0 + c16 * 4);
        }
        #pragma unroll
        for (int t = 0; t < 4; t++) {
            int e = tid + t * 256;
            int r = e >> 5, c16 = e & 31;
            cp_async16(bs_b + (uint32_t)buf * BBUF * 4 + (uint32_t)(r * BSTR + c16 * 4) * 4,
                       W + (size_t)(k0 + r) * DDIM + c16 * 4);
        }
    };

    issue(0, 0);
    CP_COMMIT();

    const int NCH = EDIM / GKC;   // 64
    for (int c = 0; c < NCH; c++) {
        if (c < NCH - 1) { issue(c + 1, (c + 1) & 1); CP_COMMIT(); CP_WAIT(1); }
        else             { CP_WAIT(0); }
        __syncthreads();

        const float* Asb = As + (c & 1) * ABUF;
        const float* Bsb = Bs + (c & 1) * BBUF;

        #pragma unroll
        for (int ks = 0; ks < GKC / 8; ks++) {
            const int ak = ks * 8 + (lane & 3);
            uint32_t a[2][4];
            #pragma unroll
            for (int mt = 0; mt < 2; mt++) {
                const int ar = wm * 32 + mt * 16 + (lane >> 2);
                a[mt][0] = f2tf32(Asb[ar * ASTR + ak]);
                a[mt][1] = f2tf32(Asb[(ar + 8) * ASTR + ak]);
                a[mt][2] = f2tf32(Asb[ar * ASTR + ak + 4]);
                a[mt][3] = f2tf32(Asb[(ar + 8) * ASTR + ak + 4]);
            }
            uint32_t bf[8][2];
            const int bn0 = wn * 64 + (lane >> 2);
            #pragma unroll
            for (int nt = 0; nt < 8; nt++) {
                bf[nt][0] = f2tf32(Bsb[ak * BSTR + bn0 + nt * 8]);
                bf[nt][1] = f2tf32(Bsb[(ak + 4) * BSTR + bn0 + nt * 8]);
            }
            #pragma unroll
            for (int mt = 0; mt < 2; mt++)
                #pragma unroll
                for (int nt = 0; nt < 8; nt++)
                    mma_tf32(acc[mt][nt], a[mt], bf[nt]);
        }
        __syncthreads();
    }

    // Epilogue: fp16 stores; Q pre-scaled by log2(e)/sqrt(D).
    const float sc = (z == 0) ? 0.1275413575339156f : 1.0f;  // log2e/sqrt(128)
    #pragma unroll
    for (int mt = 0; mt < 2; mt++) {
        const int r0 = row0 + wm * 32 + mt * 16 + (lane >> 2);
        #pragma unroll
        for (int nt = 0; nt < 8; nt++) {
            const int col = wn * 64 + nt * 8 + 2 * (lane & 3);
            *(uint32_t*)(Y + (size_t)r0 * DDIM + col) =
                packh2(acc[mt][nt][0] * sc, acc[mt][nt][1] * sc);
            *(uint32_t*)(Y + (size_t)(r0 + 8) * DDIM + col) =
                packh2(acc[mt][nt][2] * sc, acc[mt][nt][3] * sc);
        }
    }
}

// ---------------------------------------------------------------------------
// Kernel 2: causal flash attention, fp16 mma (m16n8k16) + ldmatrix.
//   BQ=64 (4 warps x 16 rows), BKV=64. Q fragments in registers.
//   K/V fp16, cp.async double-buffered. Base-2 online softmax.
// ---------------------------------------------------------------------------
#define BQ     64
#define BKV    64
#define QSTRH  136                     // halves per Q row (272B, conflict-free)
#define KSTRH  136                     // halves per K/V row
#define PSTRH  72                      // halves per P row (144B, conflict-free)
#define QBYTES (BQ * QSTRH * 2)        // 17408
#define KBYTES (BKV * KSTRH * 2)       // 17408 per stage
#define PBYTES (BQ * PSTRH * 2)        // 9216
#define ATT_SMEM (QBYTES + 4 * KBYTES + PBYTES)   // 96256 bytes

__global__ __launch_bounds__(128, 2)
void attn_mma_kernel(float* __restrict__ out)
{
    extern __shared__ char smc[];
    const uint32_t qs_b = smem_u32(smc);
    const uint32_t kb_b = qs_b + QBYTES;
    const uint32_t vb_b = kb_b + 2 * KBYTES;
    const uint32_t ps_b = vb_b + 2 * KBYTES;

    // bid and bid+148 land on the same SM; pair big with small.
    const int bid  = blockIdx.x;
    const int rank = (bid < 148) ? bid : (403 - bid);
    const int qi   = 63 - (rank >> 2);
    const int b    = rank & 3;

    const int tid  = threadIdx.x;
    const int lane = tid & 31;
    const int wid  = tid >> 5;

    const __half* Qg = g_Q + ((size_t)b * TSEQ + (size_t)qi * BQ) * DDIM;
    const __half* Kg = g_K + (size_t)b * TSEQ * DDIM;
    const __half* Vg = g_V + (size_t)b * TSEQ * DDIM;

    // --- async load: Q tile (group 0), then KV tile 0 (group 1) ---
    #pragma unroll
    for (int t = 0; t < 8; t++) {          // 64 rows x 16 chunks of 8 halves
        int e = tid + t * 128;
        int r = e >> 4, c16 = e & 15;
        cp_async16(qs_b + (uint32_t)(r * QSTRH + c16 * 8) * 2,
                   Qg + (size_t)r * DDIM + c16 * 8);
    }
    CP_COMMIT();

    auto issue_kv = [&](int j, int buf) {
        const __half* kg = Kg + (size_t)j * BKV * DDIM;
        const __half* vg = Vg + (size_t)j * BKV * DDIM;
        const uint32_t kd = kb_b + (uint32_t)buf * KBYTES;
        const uint32_t vd = vb_b + (uint32_t)buf * KBYTES;
        #pragma unroll
        for (int t = 0; t < 8; t++) {
            int e = tid + t * 128;
            int r = e >> 4, c16 = e & 15;
            uint32_t off = (uint32_t)(r * KSTRH + c16 * 8) * 2;
            cp_async16(kd + off, kg + (size_t)r * DDIM + c16 * 8);
            cp_async16(vd + off, vg + (size_t)r * DDIM + c16 * 8);
        }
    };

    issue_kv(0, 0);
    CP_COMMIT();

    // Q fragments -> registers (8 k16-chunks x 4 regs).
    CP_WAIT(1);            // Q group done
    __syncthreads();
    uint32_t qf[8][4];
    {
        const uint32_t base = qs_b +
            (uint32_t)((wid * 16 + (lane & 15)) * QSTRH + (lane >> 4) * 8) * 2;
        #pragma unroll
        for (int ks = 0; ks < 8; ks++)
            ldsm_x4(qf[ks][0], qf[ks][1], qf[ks][2], qf[ks][3],
                    base + (uint32_t)(ks * 16) * 2);
    }

    float m0 = -1e30f, m1 = -1e30f, l0 = 0.0f, l1 = 0.0f;
    float o[16][4];
    #pragma unroll
    for (int nt = 0; nt < 16; nt++)
        #pragma unroll
        for (int q = 0; q < 4; q++)
            o[nt][q] = 0.0f;

    const int jmax = qi;
    for (int j = 0; j <= jmax; j++) {
        if (j < jmax) { issue_kv(j + 1, (j + 1) & 1); CP_COMMIT(); CP_WAIT(1); }
        else          { CP_WAIT(0); }
        __syncthreads();

        const uint32_t ksb = kb_b + (uint32_t)(j & 1) * KBYTES;
        const uint32_t vsb = vb_b + (uint32_t)(j & 1) * KBYTES;

        const bool active = (j * BKV <= qi * BQ + wid * 16 + 15);
        if (active) {
            // ---- S = Q K^T : 8 k16-chunks x 8 n-tiles ----
            float s[8][4];
            #pragma unroll
            for (int nt = 0; nt < 8; nt++)
                #pragma unroll
                for (int q = 0; q < 4; q++)
                    s[nt][q] = 0.0f;

            // K fragment address (n-pair p, chunk ks):
            //   row n = p*16 + (lane&7) + (lane>>4)*8 ; col = ks*16 + ((lane>>3)&1)*8
            const uint32_t krow = (uint32_t)((lane & 7) + ((lane >> 4) << 3));
            const uint32_t kcol = (uint32_t)(((lane >> 3) & 1) << 3);
            #pragma unroll
            for (int ks = 0; ks < 8; ks++) {
                #pragma unroll
                for (int p = 0; p < 4; p++) {
                    uint32_t b0, b1, b2, b3;
                    ldsm_x4(b0, b1, b2, b3,
                            ksb + (uint32_t)((p * 16 + krow) * KSTRH + ks * 16 + kcol) * 2);
                    uint32_t bl[2] = {b0, b1};
                    uint32_t bh[2] = {b2, b3};
                    mma_f16(s[2 * p],     qf[ks], bl);
                    mma_f16(s[2 * p + 1], qf[ks], bh);
                }
            }

            // Causal mask (diagonal-straddling tiles only).
            if (j * BKV + BKV - 1 > qi * BQ + wid * 16) {
                const int grow = qi * BQ + wid * 16 + (lane >> 2);
                #pragma unroll
                for (int nt = 0; nt < 8; nt++) {
                    const int gc = j * BKV + nt * 8 + 2 * (lane & 3);
                    if (gc     > grow)     s[nt][0] = -1e30f;
                    if (gc + 1 > grow)     s[nt][1] = -1e30f;
                    if (gc     > grow + 8) s[nt][2] = -1e30f;
                    if (gc + 1 > grow + 8) s[nt][3] = -1e30f;
                }
            }

            // ---- Online softmax in base 2 (2 rows/thread, quad reduce) ----
            float mx0 = -1e30f, mx1 = -1e30f;
            #pragma unroll
            for (int nt = 0; nt < 8; nt++) {
                mx0 = fmaxf(mx0, fmaxf(s[nt][0], s[nt][1]));
                mx1 = fmaxf(mx1, fmaxf(s[nt][2], s[nt][3]));
            }
            mx0 = fmaxf(mx0, __shfl_xor_sync(0xffffffffu, mx0, 1));
            mx0 = fmaxf(mx0, __shfl_xor_sync(0xffffffffu, mx0, 2));
            mx1 = fmaxf(mx1, __shfl_xor_sync(0xffffffffu, mx1, 1));
            mx1 = fmaxf(mx1, __shfl_xor_sync(0xffffffffu, mx1, 2));

            const float mn0 = fmaxf(m0, mx0);
            const float mn1 = fmaxf(m1, mx1);
            const float f0 = ex2f(m0 - mn0);
            const float f1 = ex2f(m1 - mn1);

            float sum0 = 0.0f, sum1 = 0.0f;
            #pragma unroll
            for (int nt = 0; nt < 8; nt++) {
                s[nt][0] = ex2f(s[nt][0] - mn0);
                s[nt][1] = ex2f(s[nt][1] - mn0);
                s[nt][2] = ex2f(s[nt][2] - mn1);
                s[nt][3] = ex2f(s[nt][3] - mn1);
                sum0 += s[nt][0] + s[nt][1];
                sum1 += s[nt][2] + s[nt][3];
            }
            sum0 += __shfl_xor_sync(0xffffffffu, sum0, 1);
            sum0 += __shfl_xor_sync(0xffffffffu, sum0, 2);
            sum1 += __shfl_xor_sync(0xffffffffu, sum1, 1);
            sum1 += __shfl_xor_sync(0xffffffffu, sum1, 2);

            l0 = l0 * f0 + sum0;  m0 = mn0;
            l1 = l1 * f1 + sum1;  m1 = mn1;

            #pragma unroll
            for (int nt = 0; nt < 16; nt++) {
                o[nt][0] *= f0; o[nt][1] *= f0;
                o[nt][2] *= f1; o[nt][3] *= f1;
            }

            // Stage P (fp16), warp-private rows.
            {
                const int pr = wid * 16 + (lane >> 2);
                const int pc = 2 * (lane & 3);
                #pragma unroll
                for (int nt = 0; nt < 8; nt++) {
                    *(uint32_t*)(smc + (ps_b - qs_b) +
                        (uint32_t)(pr * PSTRH + nt * 8 + pc) * 2) =
                        packh2(s[nt][0], s[nt][1]);
                    *(uint32_t*)(smc + (ps_b - qs_b) +
                        (uint32_t)((pr + 8) * PSTRH + nt * 8 + pc) * 2) =
                        packh2(s[nt][2], s[nt][3]);
                }
            }
            __syncwarp();

            // ---- O += P V : 4 k16-chunks x 16 n-tiles ----
            const uint32_t pbase = ps_b +
                (uint32_t)((wid * 16 + (lane & 15)) * PSTRH + (lane >> 4) * 8) * 2;
            const uint32_t vrow = (uint32_t)((lane & 7) + (((lane >> 3) & 1) << 3));
            const uint32_t vcol = (uint32_t)((lane >> 4) << 3);
            #pragma unroll
            for (int kc = 0; kc < 4; kc++) {
                uint32_t a[4];
                ldsm_x4(a[0], a[1], a[2], a[3], pbase + (uint32_t)(kc * 16) * 2);
                #pragma unroll
                for (int p = 0; p < 8; p++) {
                    uint32_t b0, b1, b2, b3;
                    ldsm_x4_t(b0, b1, b2, b3,
                              vsb + (uint32_t)((kc * 16 + vrow) * KSTRH + p * 16 + vcol) * 2);
                    uint32_t bl[2] = {b0, b1};
                    uint32_t bh[2] = {b2, b3};
                    mma_f16(o[2 * p],     a, bl);
                    mma_f16(o[2 * p + 1], a, bh);
                }
            }
        }
        __syncthreads();
    }

    // Epilogue
    const float inv0 = 1.0f / l0;
    const float inv1 = 1.0f / l1;
    const int rg = qi * BQ + wid * 16 + (lane >> 2);
    float* Og = out + (size_t)b * TSEQ * DDIM;
    #pragma unroll
    for (int nt = 0; nt < 16; nt++) {
        const int col = nt * 8 + 2 * (lane & 3);
        float2 lo = make_float2(o[nt][0] * inv0, o[nt][1] * inv0);
        float2 hi = make_float2(o[nt][2] * inv1, o[nt][3] * inv1);
        *(float2*)(Og + (size_t)rg * DDIM + col)       = lo;
        *(float2*)(Og + (size_t)(rg + 8) * DDIM + col) = hi;
    }
}

// ---------------------------------------------------------------------------
// Launch
// ---------------------------------------------------------------------------
extern "C" void kernel_launch(void* const* d_in, const int* in_sizes, int n_in,
                              void* d_out, int out_size)
{
    (void)in_sizes; (void)n_in; (void)out_size;
    const float* x  = (const float*)d_in[0];
    const float* Wq = (const float*)d_in[1];
    const float* Wk = (const float*)d_in[2];
    const float* Wv = (const float*)d_in[3];
    float* out = (float*)d_out;

    cudaFuncSetAttribute(qkv_mma_kernel,
                         cudaFuncAttributeMaxDynamicSharedMemorySize, GEMM_SMEM);
    dim3 g1(3, MTOT / 128);
    qkv_mma_kernel<<<g1, 256, GEMM_SMEM>>>(x, Wq, Wk, Wv);

    cudaFuncSetAttribute(attn_mma_kernel,
                         cudaFuncAttributeMaxDynamicSharedMemorySize, ATT_SMEM);
    attn_mma_kernel<<<(TSEQ / BQ) * BATCH, 128, ATT_SMEM>>>(out);
}

// round 7
// speedup vs baseline: 11.4711x; 1.4526x over previous
#include <cuda_runtime.h>
#include <cuda_fp16.h>
#include <cstdint>
#include <cstddef>

// ---------------------------------------------------------------------------
// Problem constants
// ---------------------------------------------------------------------------
#define BATCH 4
#define TSEQ  4096
#define EDIM  2048
#define DDIM  128
#define MTOT  (BATCH * TSEQ)   // 16384

// fp16 copies of inputs (pre-pass) and QKV outputs.
__device__ __half g_X [MTOT * EDIM];        // 64 MB
__device__ __half g_Wh[3 * EDIM * DDIM];    // 4.5 MB
__device__ __half g_Q [MTOT * DDIM];
__device__ __half g_K [MTOT * DDIM];
__device__ __half g_V [MTOT * DDIM];

// ---------------------------------------------------------------------------
// Helpers
// ---------------------------------------------------------------------------
__device__ __forceinline__ uint32_t smem_u32(const void* p) {
    uint32_t a;
    asm("{ .reg .u64 t; cvta.to.shared.u64 t, %1; cvt.u32.u64 %0, t; }"
        : "=r"(a) : "l"(p));
    return a;
}

__device__ __forceinline__ void cp_async16(uint32_t saddr, const void* gptr) {
    asm volatile("cp.async.cg.shared.global [%0], [%1], 16;"
                 :: "r"(saddr), "l"(gptr));
}
#define CP_COMMIT() asm volatile("cp.async.commit_group;" ::: "memory")
#define CP_WAIT(n)  asm volatile("cp.async.wait_group %0;" :: "n"(n) : "memory")

__device__ __forceinline__ float ex2f(float x) {
    float r;
    asm("ex2.approx.ftz.f32 %0, %1;" : "=f"(r) : "f"(x));
    return r;
}

__device__ __forceinline__ uint32_t packh2(float a, float b) {
    __half2 h = __floats2half2_rn(a, b);   // low = a, high = b
    return *(uint32_t*)&h;
}

// fp16 mma, fp32 accumulate: D(16x8) += A(16x16) * B(16x8)
__device__ __forceinline__ void mma_f16(float* d, const uint32_t* a, const uint32_t* b) {
    asm volatile(
        "mma.sync.aligned.m16n8k16.row.col.f32.f16.f16.f32 "
        "{%0,%1,%2,%3}, {%4,%5,%6,%7}, {%8,%9}, {%0,%1,%2,%3};\n"
        : "+f"(d[0]), "+f"(d[1]), "+f"(d[2]), "+f"(d[3])
        : "r"(a[0]), "r"(a[1]), "r"(a[2]), "r"(a[3]),
          "r"(b[0]), "r"(b[1]));
}

__device__ __forceinline__ void ldsm_x4(uint32_t& r0, uint32_t& r1,
                                        uint32_t& r2, uint32_t& r3, uint32_t a) {
    asm volatile("ldmatrix.sync.aligned.m8n8.x4.shared.b16 {%0,%1,%2,%3}, [%4];"
                 : "=r"(r0), "=r"(r1), "=r"(r2), "=r"(r3) : "r"(a));
}
__device__ __forceinline__ void ldsm_x4_t(uint32_t& r0, uint32_t& r1,
                                          uint32_t& r2, uint32_t& r3, uint32_t a) {
    asm volatile("ldmatrix.sync.aligned.m8n8.x4.trans.shared.b16 {%0,%1,%2,%3}, [%4];"
                 : "=r"(r0), "=r"(r1), "=r"(r2), "=r"(r3) : "r"(a));
}

// ---------------------------------------------------------------------------
// Kernel 0: fp32 -> fp16 conversion pre-pass (x and the three W matrices).
//   Blocks [0, XBLK): x (8 elems/thread). Blocks [XBLK, XBLK+3*WBLK): W.
// ---------------------------------------------------------------------------
#define XBLK 16384      // 16384 * 256 * 8 = 33,554,432 = MTOT*EDIM
#define WBLK 384        //   384 * 256 * 8 =    786,432 = EDIM*DDIM

__global__ __launch_bounds__(256)
void cvt_fp16_kernel(const float* __restrict__ x,
                     const float* __restrict__ Wq,
                     const float* __restrict__ Wk,
                     const float* __restrict__ Wv)
{
    const int bx = blockIdx.x;
    const float* src;
    __half* dst;
    size_t idx;
    if (bx < XBLK) {
        src = x; dst = g_X;
        idx = ((size_t)bx * 256 + threadIdx.x) * 8;
    } else {
        const int wz = (bx - XBLK) / WBLK;
        src = (wz == 0) ? Wq : (wz == 1) ? Wk : Wv;
        dst = g_Wh + (size_t)wz * EDIM * DDIM;
        idx = ((size_t)((bx - XBLK) % WBLK) * 256 + threadIdx.x) * 8;
    }
    float4 v0 = *(const float4*)(src + idx);
    float4 v1 = *(const float4*)(src + idx + 4);
    uint4 u;
    u.x = packh2(v0.x, v0.y);
    u.y = packh2(v0.z, v0.w);
    u.z = packh2(v1.x, v1.y);
    u.w = packh2(v1.z, v1.w);
    *(uint4*)(dst + idx) = u;
}

// ---------------------------------------------------------------------------
// Kernel 1: QKV projection GEMM, fp16 mma (m16n8k16) + ldmatrix.
//   CTA tile 128x128, KC=64 halves, 8 warps (warp tile 32x64), cp.async
//   2-stage pipeline. grid (3, 128): z fastest -> Q/K/V share x tile in L2.
//   Q output pre-scaled by log2(e)/sqrt(D).
// ---------------------------------------------------------------------------
#define GKC    64
#define HASTR  72                        // halves per A row (144 B)
#define HBSTR  136                       // halves per B row (272 B)
#define ABYTES (128 * HASTR * 2)         // 18432 per stage
#define BBYTES (GKC * HBSTR * 2)         // 17408 per stage
#define GEMM_SMEM (2 * ABYTES + 2 * BBYTES)   // 71680 bytes

__global__ __launch_bounds__(256, 2)
void qkv_mma_kernel()
{
    extern __shared__ char smg[];
    const uint32_t as_b = smem_u32(smg);
    const uint32_t bs_b = as_b + 2 * ABYTES;

    const int z = blockIdx.x;
    const __half* W = g_Wh + (size_t)z * EDIM * DDIM;
    __half* Y       = (z == 0) ? g_Q : (z == 1) ? g_K : g_V;
    const int row0 = blockIdx.y * 128;

    const int tid  = threadIdx.x;
    const int lane = tid & 31;
    const int wid  = tid >> 5;
    const int wm   = wid >> 1;    // 0..3
    const int wn   = wid & 1;     // 0..1

    float acc[2][8][4];
    #pragma unroll
    for (int mt = 0; mt < 2; mt++)
        #pragma unroll
        for (int nt = 0; nt < 8; nt++)
            #pragma unroll
            for (int q = 0; q < 4; q++)
                acc[mt][nt][q] = 0.0f;

    auto issue = [&](int c, int buf) {
        const int k0 = c * GKC;
        // A: 128 rows x 8 chunks of 8 halves
        #pragma unroll
        for (int t = 0; t < 4; t++) {
            int e = tid + t * 256;
            int r = e >> 3, c8 = e & 7;
            cp_async16(as_b + (uint32_t)buf * ABYTES + (uint32_t)(r * HASTR + c8 * 8) * 2,
                       g_X + (size_t)(row0 + r) * EDIM + k0 + c8 * 8);
        }
        // B: 64 rows x 16 chunks of 8 halves
        #pragma unroll
        for (int t = 0; t < 4; t++) {
            int e = tid + t * 256;
            int r = e >> 4, c8 = e & 15;
            cp_async16(bs_b + (uint32_t)buf * BBYTES + (uint32_t)(r * HBSTR + c8 * 8) * 2,
                       W + (size_t)(k0 + r) * DDIM + c8 * 8);
        }
    };

    issue(0, 0);
    CP_COMMIT();

    // ldmatrix lane-address components
    const uint32_t arow = (uint32_t)(lane & 15);
    const uint32_t acol = (uint32_t)((lane >> 4) << 3);
    const uint32_t brow = (uint32_t)((lane & 7) + (((lane >> 3) & 1) << 3));
    const uint32_t bcol = (uint32_t)((lane >> 4) << 3);

    const int NCH = EDIM / GKC;   // 32
    for (int c = 0; c < NCH; c++) {
        if (c < NCH - 1) { issue(c + 1, (c + 1) & 1); CP_COMMIT(); CP_WAIT(1); }
        else             { CP_WAIT(0); }
        __syncthreads();

        const uint32_t asb = as_b + (uint32_t)(c & 1) * ABYTES;
        const uint32_t bsb = bs_b + (uint32_t)(c & 1) * BBYTES;

        #pragma unroll
        for (int ks = 0; ks < GKC / 16; ks++) {       // 4 k16-steps
            uint32_t a[2][4];
            #pragma unroll
            for (int mt = 0; mt < 2; mt++)
                ldsm_x4(a[mt][0], a[mt][1], a[mt][2], a[mt][3],
                        asb + (uint32_t)((wm * 32 + mt * 16 + arow) * HASTR
                                         + ks * 16 + acol) * 2);
            #pragma unroll
            for (int p = 0; p < 4; p++) {             // 4 n16-pairs -> n=64
                uint32_t b0, b1, b2, b3;
                ldsm_x4_t(b0, b1, b2, b3,
                          bsb + (uint32_t)((ks * 16 + brow) * HBSTR
                                           + wn * 64 + p * 16 + bcol) * 2);
                uint32_t bl[2] = {b0, b1};
                uint32_t bh[2] = {b2, b3};
                #pragma unroll
                for (int mt = 0; mt < 2; mt++) {
                    mma_f16(acc[mt][2 * p],     a[mt], bl);
                    mma_f16(acc[mt][2 * p + 1], a[mt], bh);
                }
            }
        }
        __syncthreads();
    }

    // Epilogue: fp16 stores; Q pre-scaled by log2(e)/sqrt(D).
    const float sc = (z == 0) ? 0.1275413575339156f : 1.0f;
    #pragma unroll
    for (int mt = 0; mt < 2; mt++) {
        const int r0 = row0 + wm * 32 + mt * 16 + (lane >> 2);
        #pragma unroll
        for (int nt = 0; nt < 8; nt++) {
            const int col = wn * 64 + nt * 8 + 2 * (lane & 3);
            *(uint32_t*)(Y + (size_t)r0 * DDIM + col) =
                packh2(acc[mt][nt][0] * sc, acc[mt][nt][1] * sc);
            *(uint32_t*)(Y + (size_t)(r0 + 8) * DDIM + col) =
                packh2(acc[mt][nt][2] * sc, acc[mt][nt][3] * sc);
        }
    }
}

// ---------------------------------------------------------------------------
// Kernel 2: causal flash attention, fp16 mma (m16n8k16) + ldmatrix.
//   (unchanged from round 6: BQ=64, BKV=64, base-2 online softmax)
// ---------------------------------------------------------------------------
#define BQ     64
#define BKV    64
#define QSTRH  136
#define KSTRH  136
#define PSTRH  72
#define QBYTES (BQ * QSTRH * 2)
#define KBYTES (BKV * KSTRH * 2)
#define PBYTES (BQ * PSTRH * 2)
#define ATT_SMEM (QBYTES + 4 * KBYTES + PBYTES)   // 96256 bytes

__global__ __launch_bounds__(128, 2)
void attn_mma_kernel(float* __restrict__ out)
{
    extern __shared__ char smc[];
    const uint32_t qs_b = smem_u32(smc);
    const uint32_t kb_b = qs_b + QBYTES;
    const uint32_t vb_b = kb_b + 2 * KBYTES;
    const uint32_t ps_b = vb_b + 2 * KBYTES;

    const int bid  = blockIdx.x;
    const int rank = (bid < 148) ? bid : (403 - bid);
    const int qi   = 63 - (rank >> 2);
    const int b    = rank & 3;

    const int tid  = threadIdx.x;
    const int lane = tid & 31;
    const int wid  = tid >> 5;

    const __half* Qg = g_Q + ((size_t)b * TSEQ + (size_t)qi * BQ) * DDIM;
    const __half* Kg = g_K + (size_t)b * TSEQ * DDIM;
    const __half* Vg = g_V + (size_t)b * TSEQ * DDIM;

    #pragma unroll
    for (int t = 0; t < 8; t++) {
        int e = tid + t * 128;
        int r = e >> 4, c16 = e & 15;
        cp_async16(qs_b + (uint32_t)(r * QSTRH + c16 * 8) * 2,
                   Qg + (size_t)r * DDIM + c16 * 8);
    }
    CP_COMMIT();

    auto issue_kv = [&](int j, int buf) {
        const __half* kg = Kg + (size_t)j * BKV * DDIM;
        const __half* vg = Vg + (size_t)j * BKV * DDIM;
        const uint32_t kd = kb_b + (uint32_t)buf * KBYTES;
        const uint32_t vd = vb_b + (uint32_t)buf * KBYTES;
        #pragma unroll
        for (int t = 0; t < 8; t++) {
            int e = tid + t * 128;
            int r = e >> 4, c16 = e & 15;
            uint32_t off = (uint32_t)(r * KSTRH + c16 * 8) * 2;
            cp_async16(kd + off, kg + (size_t)r * DDIM + c16 * 8);
            cp_async16(vd + off, vg + (size_t)r * DDIM + c16 * 8);
        }
    };

    issue_kv(0, 0);
    CP_COMMIT();

    CP_WAIT(1);
    __syncthreads();
    uint32_t qf[8][4];
    {
        const uint32_t base = qs_b +
            (uint32_t)((wid * 16 + (lane & 15)) * QSTRH + (lane >> 4) * 8) * 2;
        #pragma unroll
        for (int ks = 0; ks < 8; ks++)
            ldsm_x4(qf[ks][0], qf[ks][1], qf[ks][2], qf[ks][3],
                    base + (uint32_t)(ks * 16) * 2);
    }

    float m0 = -1e30f, m1 = -1e30f, l0 = 0.0f, l1 = 0.0f;
    float o[16][4];
    #pragma unroll
    for (int nt = 0; nt < 16; nt++)
        #pragma unroll
        for (int q = 0; q < 4; q++)
            o[nt][q] = 0.0f;

    const int jmax = qi;
    for (int j = 0; j <= jmax; j++) {
        if (j < jmax) { issue_kv(j + 1, (j + 1) & 1); CP_COMMIT(); CP_WAIT(1); }
        else          { CP_WAIT(0); }
        __syncthreads();

        const uint32_t ksb = kb_b + (uint32_t)(j & 1) * KBYTES;
        const uint32_t vsb = vb_b + (uint32_t)(j & 1) * KBYTES;

        const bool active = (j * BKV <= qi * BQ + wid * 16 + 15);
        if (active) {
            float s[8][4];
            #pragma unroll
            for (int nt = 0; nt < 8; nt++)
                #pragma unroll
                for (int q = 0; q < 4; q++)
                    s[nt][q] = 0.0f;

            const uint32_t krow = (uint32_t)((lane & 7) + ((lane >> 4) << 3));
            const uint32_t kcol = (uint32_t)(((lane >> 3) & 1) << 3);
            #pragma unroll
            for (int ks = 0; ks < 8; ks++) {
                #pragma unroll
                for (int p = 0; p < 4; p++) {
                    uint32_t b0, b1, b2, b3;
                    ldsm_x4(b0, b1, b2, b3,
                            ksb + (uint32_t)((p * 16 + krow) * KSTRH + ks * 16 + kcol) * 2);
                    uint32_t bl[2] = {b0, b1};
                    uint32_t bh[2] = {b2, b3};
                    mma_f16(s[2 * p],     qf[ks], bl);
                    mma_f16(s[2 * p + 1], qf[ks], bh);
                }
            }

            if (j * BKV + BKV - 1 > qi * BQ + wid * 16) {
                const int grow = qi * BQ + wid * 16 + (lane >> 2);
                #pragma unroll
                for (int nt = 0; nt < 8; nt++) {
                    const int gc = j * BKV + nt * 8 + 2 * (lane & 3);
                    if (gc     > grow)     s[nt][0] = -1e30f;
                    if (gc + 1 > grow)     s[nt][1] = -1e30f;
                    if (gc     > grow + 8) s[nt][2] = -1e30f;
                    if (gc + 1 > grow + 8) s[nt][3] = -1e30f;
                }
            }

            float mx0 = -1e30f, mx1 = -1e30f;
            #pragma unroll
            for (int nt = 0; nt < 8; nt++) {
                mx0 = fmaxf(mx0, fmaxf(s[nt][0], s[nt][1]));
                mx1 = fmaxf(mx1, fmaxf(s[nt][2], s[nt][3]));
            }
            mx0 = fmaxf(mx0, __shfl_xor_sync(0xffffffffu, mx0, 1));
            mx0 = fmaxf(mx0, __shfl_xor_sync(0xffffffffu, mx0, 2));
            mx1 = fmaxf(mx1, __shfl_xor_sync(0xffffffffu, mx1, 1));
            mx1 = fmaxf(mx1, __shfl_xor_sync(0xffffffffu, mx1, 2));

            const float mn0 = fmaxf(m0, mx0);
            const float mn1 = fmaxf(m1, mx1);
            const float f0 = ex2f(m0 - mn0);
            const float f1 = ex2f(m1 - mn1);

            float sum0 = 0.0f, sum1 = 0.0f;
            #pragma unroll
            for (int nt = 0; nt < 8; nt++) {
                s[nt][0] = ex2f(s[nt][0] - mn0);
                s[nt][1] = ex2f(s[nt][1] - mn0);
                s[nt][2] = ex2f(s[nt][2] - mn1);
                s[nt][3] = ex2f(s[nt][3] - mn1);
                sum0 += s[nt][0] + s[nt][1];
                sum1 += s[nt][2] + s[nt][3];
            }
            sum0 += __shfl_xor_sync(0xffffffffu, sum0, 1);
            sum0 += __shfl_xor_sync(0xffffffffu, sum0, 2);
            sum1 += __shfl_xor_sync(0xffffffffu, sum1, 1);
            sum1 += __shfl_xor_sync(0xffffffffu, sum1, 2);

            l0 = l0 * f0 + sum0;  m0 = mn0;
            l1 = l1 * f1 + sum1;  m1 = mn1;

            #pragma unroll
            for (int nt = 0; nt < 16; nt++) {
                o[nt][0] *= f0; o[nt][1] *= f0;
                o[nt][2] *= f1; o[nt][3] *= f1;
            }

            {
                const int pr = wid * 16 + (lane >> 2);
                const int pc = 2 * (lane & 3);
                #pragma unroll
                for (int nt = 0; nt < 8; nt++) {
                    *(uint32_t*)(smc + (ps_b - qs_b) +
                        (uint32_t)(pr * PSTRH + nt * 8 + pc) * 2) =
                        packh2(s[nt][0], s[nt][1]);
                    *(uint32_t*)(smc + (ps_b - qs_b) +
                        (uint32_t)((pr + 8) * PSTRH + nt * 8 + pc) * 2) =
                        packh2(s[nt][2], s[nt][3]);
                }
            }
            __syncwarp();

            const uint32_t pbase = ps_b +
                (uint32_t)((wid * 16 + (lane & 15)) * PSTRH + (lane >> 4) * 8) * 2;
            const uint32_t vrow = (uint32_t)((lane & 7) + (((lane >> 3) & 1) << 3));
            const uint32_t vcol = (uint32_t)((lane >> 4) << 3);
            #pragma unroll
            for (int kc = 0; kc < 4; kc++) {
                uint32_t a[4];
                ldsm_x4(a[0], a[1], a[2], a[3], pbase + (uint32_t)(kc * 16) * 2);
                #pragma unroll
                for (int p = 0; p < 8; p++) {
                    uint32_t b0, b1, b2, b3;
                    ldsm_x4_t(b0, b1, b2, b3,
                              vsb + (uint32_t)((kc * 16 + vrow) * KSTRH + p * 16 + vcol) * 2);
                    uint32_t bl[2] = {b0, b1};
                    uint32_t bh[2] = {b2, b3};
                    mma_f16(o[2 * p],     a, bl);
                    mma_f16(o[2 * p + 1], a, bh);
                }
            }
        }
        __syncthreads();
    }

    const float inv0 = 1.0f / l0;
    const float inv1 = 1.0f / l1;
    const int rg = qi * BQ + wid * 16 + (lane >> 2);
    float* Og = out + (size_t)b * TSEQ * DDIM;
    #pragma unroll
    for (int nt = 0; nt < 16; nt++) {
        const int col = nt * 8 + 2 * (lane & 3);
        float2 lo = make_float2(o[nt][0] * inv0, o[nt][1] * inv0);
        float2 hi = make_float2(o[nt][2] * inv1, o[nt][3] * inv1);
        *(float2*)(Og + (size_t)rg * DDIM + col)       = lo;
        *(float2*)(Og + (size_t)(rg + 8) * DDIM + col) = hi;
    }
}

// ---------------------------------------------------------------------------
// Launch
// ---------------------------------------------------------------------------
extern "C" void kernel_launch(void* const* d_in, const int* in_sizes, int n_in,
                              void* d_out, int out_size)
{
    (void)in_sizes; (void)n_in; (void)out_size;
    const float* x  = (const float*)d_in[0];
    const float* Wq = (const float*)d_in[1];
    const float* Wk = (const float*)d_in[2];
    const float* Wv = (const float*)d_in[3];
    float* out = (float*)d_out;

    cvt_fp16_kernel<<<XBLK + 3 * WBLK, 256>>>(x, Wq, Wk, Wv);

    cudaFuncSetAttribute(qkv_mma_kernel,
                         cudaFuncAttributeMaxDynamicSharedMemorySize, GEMM_SMEM);
    dim3 g1(3, MTOT / 128);
    qkv_mma_kernel<<<g1, 256, GEMM_SMEM>>>();

    cudaFuncSetAttribute(attn_mma_kernel,
                         cudaFuncAttributeMaxDynamicSharedMemorySize, ATT_SMEM);
    attn_mma_kernel<<<(TSEQ / BQ) * BATCH, 128, ATT_SMEM>>>(out);
}